// round 5
// baseline (speedup 1.0000x reference)
#include <cuda_runtime.h>
#include <cuda_fp16.h>
#include <math.h>
#include <cstdint>

#define H_DIM 768
#define D_DIM 384
#define L_DIM 128
#define B_MAX 32768

// -------- scratch (module globals; no runtime allocation) --------
__device__ float  g_x2[B_MAX];
__device__ float  g_y2[L_DIM];
__device__ __half g_Ah[(size_t)B_MAX * H_DIM];   // cls in fp16
__device__ __half g_Xh[(size_t)B_MAX * D_DIM];   // x in fp16
__device__ __half g_Wth[(size_t)D_DIM * H_DIM];  // W^T in fp16 [D][H]
__device__ __half g_Yh[(size_t)L_DIM * D_DIM];   // Y in fp16 [L][D]

// ---------------- helpers ----------------
__device__ __forceinline__ uint32_t smem_u32(const void* p) {
    uint32_t a;
    asm("{ .reg .u64 t; cvta.to.shared.u64 t, %1; cvt.u32.u64 %0, t; }" : "=r"(a) : "l"(p));
    return a;
}
__device__ __forceinline__ void cp_async16(uint32_t s, const void* g) {
    asm volatile("cp.async.cg.shared.global [%0], [%1], 16;" :: "r"(s), "l"(g));
}
#define CP_COMMIT asm volatile("cp.async.commit_group;" ::: "memory")
#define CP_WAIT1  asm volatile("cp.async.wait_group 1;" ::: "memory")
#define CP_WAIT0  asm volatile("cp.async.wait_group 0;" ::: "memory")

__device__ __forceinline__ void mma_fp16(float* d, const uint32_t* a, const uint32_t* b) {
    asm volatile(
        "mma.sync.aligned.m16n8k16.row.col.f32.f16.f16.f32 "
        "{%0,%1,%2,%3}, {%4,%5,%6,%7}, {%8,%9}, {%0,%1,%2,%3};"
        : "+f"(d[0]), "+f"(d[1]), "+f"(d[2]), "+f"(d[3])
        : "r"(a[0]), "r"(a[1]), "r"(a[2]), "r"(a[3]), "r"(b[0]), "r"(b[1]));
}

#define ASTR_H 40                            // 32 k-halves + 8 pad (80B rows, conflict-free)
#define TILE_HALVES (128 * ASTR_H)           // one 128x32 tile
#define STAGE_HALVES (2 * TILE_HALVES)       // A tile then B tile
#define STAGE_BYTES  (STAGE_HALVES * 2)
#define SMEM_TOTAL   (2 * STAGE_BYTES)       // 40960 B

// issue cp.async for one 128x32 A tile + 128x32 B tile (fp16, [mn][k] stride ASTR_H)
__device__ __forceinline__ void stage_loads_h(uint32_t sstage, const __half* Ag,
                                              const __half* Bg, int ldA, int ldB, int tid) {
#pragma unroll
    for (int i = 0; i < 2; ++i) {
        int idx = i * 256 + tid;
        int row = idx >> 2, k8 = idx & 3;           // 4 chunks of 8 halves per row
        cp_async16(sstage + (uint32_t)((row * ASTR_H + k8 * 8) * 2),
                   Ag + (size_t)row * ldA + k8 * 8);
        cp_async16(sstage + (uint32_t)((TILE_HALVES + row * ASTR_H + k8 * 8) * 2),
                   Bg + (size_t)row * ldB + k8 * 8);
    }
}

// one k16 step: load frags + 16 mmas (warp tile 64x32)
__device__ __forceinline__ void compute_k16(const __half* As, const __half* Bs,
                                            int kb, int wm, int wn, int lane,
                                            float acc[4][4][4]) {
    const int q2 = (lane & 3) * 2;
    uint32_t af[4][4];
#pragma unroll
    for (int mt = 0; mt < 4; ++mt) {
        int r = wm + mt * 16 + (lane >> 2);
        af[mt][0] = *(const uint32_t*)(As + r * ASTR_H + kb + q2);
        af[mt][1] = *(const uint32_t*)(As + (r + 8) * ASTR_H + kb + q2);
        af[mt][2] = *(const uint32_t*)(As + r * ASTR_H + kb + 8 + q2);
        af[mt][3] = *(const uint32_t*)(As + (r + 8) * ASTR_H + kb + 8 + q2);
    }
    uint32_t bf[4][2];
#pragma unroll
    for (int nt = 0; nt < 4; ++nt) {
        int n = wn + nt * 8 + (lane >> 2);
        bf[nt][0] = *(const uint32_t*)(Bs + n * ASTR_H + kb + q2);
        bf[nt][1] = *(const uint32_t*)(Bs + n * ASTR_H + kb + 8 + q2);
    }
#pragma unroll
    for (int mt = 0; mt < 4; ++mt)
#pragma unroll
        for (int nt = 0; nt < 4; ++nt)
            mma_fp16(acc[mt][nt], af[mt], bf[nt]);
}

// ---------------- conversion kernels ----------------
__global__ void convert_A(const float* __restrict__ A) {
    size_t i = (size_t)blockIdx.x * blockDim.x + threadIdx.x;   // one per 8 floats
    const float4 v0 = ((const float4*)A)[i * 2];
    const float4 v1 = ((const float4*)A)[i * 2 + 1];
    __half2 h0 = __floats2half2_rn(v0.x, v0.y);
    __half2 h1 = __floats2half2_rn(v0.z, v0.w);
    __half2 h2 = __floats2half2_rn(v1.x, v1.y);
    __half2 h3 = __floats2half2_rn(v1.z, v1.w);
    uint4 u;
    u.x = *(uint32_t*)&h0; u.y = *(uint32_t*)&h1;
    u.z = *(uint32_t*)&h2; u.w = *(uint32_t*)&h3;
    ((uint4*)g_Ah)[i] = u;
}

__global__ void transpose_w_h(const float* __restrict__ W) {
    __shared__ float t[32][33];
    int bx = blockIdx.x * 32;  // H dim
    int by = blockIdx.y * 32;  // D dim
    int x = threadIdx.x, y = threadIdx.y;   // 32 x 8
#pragma unroll
    for (int i = 0; i < 32; i += 8)
        t[y + i][x] = W[(size_t)(bx + y + i) * D_DIM + by + x];
    __syncthreads();
#pragma unroll
    for (int i = 0; i < 32; i += 8)
        g_Wth[(size_t)(by + y + i) * H_DIM + bx + x] = __float2half_rn(t[x][y + i]);
}

__global__ void convert_Y(const float* __restrict__ Y) {
    const int j = threadIdx.x;   // 128 threads, one row each
    const float* y = Y + (size_t)j * D_DIM;
    __half* yh = g_Yh + (size_t)j * D_DIM;
    float s = 0.f;
#pragma unroll 4
    for (int d = 0; d < D_DIM; d++) {
        float v = y[d];
        s = fmaf(v, v, s);
        yh[d] = __float2half_rn(v);
    }
    g_y2[j] = s;
}

// ---------------- expmap0: warp per row ----------------
__global__ __launch_bounds__(256)
void expmap_warp(float* __restrict__ P) {
    const int warp = threadIdx.x >> 5, lane = threadIdx.x & 31;
    const int row = blockIdx.x * 8 + warp;
    float* p = P + (size_t)row * D_DIM;
    __half* xh = g_Xh + (size_t)row * D_DIM;

    float4 v[3];
    float s = 0.f;
#pragma unroll
    for (int j = 0; j < 3; ++j) {
        v[j] = ((const float4*)p)[j * 32 + lane];
        s += v[j].x * v[j].x + v[j].y * v[j].y + v[j].z * v[j].z + v[j].w * v[j].w;
    }
#pragma unroll
    for (int o = 16; o > 0; o >>= 1) s += __shfl_xor_sync(0xFFFFFFFFu, s, o);

    float nsq = s;
    float n = fmaxf(sqrtf(nsq), 1e-15f);
    float scale = tanhf(n) / n;
    if (lane == 0) g_x2[row] = nsq * scale * scale;

#pragma unroll
    for (int j = 0; j < 3; ++j) {
        float4 w = v[j];
        w.x *= scale; w.y *= scale; w.z *= scale; w.w *= scale;
        ((float4*)p)[j * 32 + lane] = w;
        __half2 h0 = __floats2half2_rn(w.x, w.y);
        __half2 h1 = __floats2half2_rn(w.z, w.w);
        uint2 u; u.x = *(uint32_t*)&h0; u.y = *(uint32_t*)&h1;
        ((uint2*)xh)[j * 32 + lane] = u;
    }
}

// ---------------- GEMM1: projected = cls @ W + b (fp16 MMA) ----------------
__global__ __launch_bounds__(256, 2)
void gemm1_mma(const float* __restrict__ bias, float* __restrict__ P)
{
    extern __shared__ __half smh[];
    const uint32_t sb = smem_u32(smh);
    const int tid = threadIdx.x, lane = tid & 31, warp = tid >> 5;
    const int wm = (warp >> 2) * 64, wn = (warp & 3) * 32;
    const int rowBase = blockIdx.y * 128, colBase = blockIdx.x * 128;

    const __half* Abase = g_Ah + (size_t)rowBase * H_DIM;
    const __half* Bbase = g_Wth + (size_t)colBase * H_DIM;

    float acc[4][4][4];
#pragma unroll
    for (int mt = 0; mt < 4; ++mt)
#pragma unroll
        for (int nt = 0; nt < 4; ++nt)
#pragma unroll
            for (int q = 0; q < 4; ++q) acc[mt][nt][q] = 0.f;

    stage_loads_h(sb, Abase, Bbase, H_DIM, H_DIM, tid);
    CP_COMMIT;

    const int NCH = H_DIM / 32;   // 24
    for (int c = 0; c < NCH; ++c) {
        const int buf = c & 1;
        if (c + 1 < NCH) {
            stage_loads_h(sb + (buf ^ 1) * STAGE_BYTES,
                          Abase + (c + 1) * 32, Bbase + (c + 1) * 32, H_DIM, H_DIM, tid);
            CP_COMMIT;
            CP_WAIT1;
        } else {
            CP_WAIT0;
        }
        __syncthreads();
        const __half* As = smh + buf * STAGE_HALVES;
        const __half* Bs = As + TILE_HALVES;
        compute_k16(As, Bs, 0,  wm, wn, lane, acc);
        compute_k16(As, Bs, 16, wm, wn, lane, acc);
        __syncthreads();
    }

#pragma unroll
    for (int mt = 0; mt < 4; ++mt) {
        int r0 = rowBase + wm + mt * 16 + (lane >> 2);
#pragma unroll
        for (int nt = 0; nt < 4; ++nt) {
            int cc = colBase + wn + nt * 8 + (lane & 3) * 2;
            float b0 = bias[cc], b1 = bias[cc + 1];
            *(float2*)&P[(size_t)r0 * D_DIM + cc] =
                make_float2(acc[mt][nt][0] + b0, acc[mt][nt][1] + b1);
            *(float2*)&P[(size_t)(r0 + 8) * D_DIM + cc] =
                make_float2(acc[mt][nt][2] + b0, acc[mt][nt][3] + b1);
        }
    }
}

// ---------------- GEMM2: xy = x @ Y^T, fused Poincare distance ----------------
__global__ __launch_bounds__(256, 2)
void gemm2_mma(float* __restrict__ logits)
{
    extern __shared__ __half smh[];
    const uint32_t sb = smem_u32(smh);
    const int tid = threadIdx.x, lane = tid & 31, warp = tid >> 5;
    const int wm = (warp >> 2) * 64, wn = (warp & 3) * 32;
    const int rowBase = blockIdx.x * 128;

    const __half* Abase = g_Xh + (size_t)rowBase * D_DIM;
    const __half* Bbase = g_Yh;

    float acc[4][4][4];
#pragma unroll
    for (int mt = 0; mt < 4; ++mt)
#pragma unroll
        for (int nt = 0; nt < 4; ++nt)
#pragma unroll
            for (int q = 0; q < 4; ++q) acc[mt][nt][q] = 0.f;

    stage_loads_h(sb, Abase, Bbase, D_DIM, D_DIM, tid);
    CP_COMMIT;

    const int NCH = D_DIM / 32;   // 12
    for (int c = 0; c < NCH; ++c) {
        const int buf = c & 1;
        if (c + 1 < NCH) {
            stage_loads_h(sb + (buf ^ 1) * STAGE_BYTES,
                          Abase + (c + 1) * 32, Bbase + (c + 1) * 32, D_DIM, D_DIM, tid);
            CP_COMMIT;
            CP_WAIT1;
        } else {
            CP_WAIT0;
        }
        __syncthreads();
        const __half* As = smh + buf * STAGE_HALVES;
        const __half* Bs = As + TILE_HALVES;
        compute_k16(As, Bs, 0,  wm, wn, lane, acc);
        compute_k16(As, Bs, 16, wm, wn, lane, acc);
        __syncthreads();
    }

    const float CLIPMAX = (1.0f - 1e-5f) * (1.0f - 1e-5f);
#pragma unroll
    for (int mt = 0; mt < 4; ++mt) {
        int r0 = rowBase + wm + mt * 16 + (lane >> 2);
        float x2a = g_x2[r0];
        float x2b = g_x2[r0 + 8];
#pragma unroll
        for (int nt = 0; nt < 4; ++nt) {
            int cc = wn + nt * 8 + (lane & 3) * 2;
            float y2a = g_y2[cc], y2b = g_y2[cc + 1];
            float o[4];
#pragma unroll
            for (int q = 0; q < 4; ++q) {
                float xy = acc[mt][nt][q];
                float x2 = (q < 2) ? x2a : x2b;
                float y2 = (q & 1) ? y2b : y2a;
                float sq  = x2 + y2 - 2.0f * xy;
                float den = 1.0f - 2.0f * xy + x2 * y2;
                float ratio = sq / den;
                ratio = fminf(fmaxf(ratio, 0.0f), CLIPMAX);
                o[q] = -2.0f * atanhf(sqrtf(ratio));
            }
            *(float2*)&logits[(size_t)r0 * L_DIM + cc]       = make_float2(o[0], o[1]);
            *(float2*)&logits[(size_t)(r0 + 8) * L_DIM + cc] = make_float2(o[2], o[3]);
        }
    }
}

// ---------------------------------------------------------------------------
extern "C" void kernel_launch(void* const* d_in, const int* in_sizes, int n_in,
                              void* d_out, int out_size)
{
    const float* cls  = (const float*)d_in[0];   // [B, 768]
    const float* Wm   = (const float*)d_in[1];   // [768, 384]
    const float* bias = (const float*)d_in[2];   // [384]
    const float* Y    = (const float*)d_in[3];   // [128, 384]

    const int B = in_sizes[0] / H_DIM;

    float* out = (float*)d_out;
    float* logits = out;                          // [B, 128]
    float* x = out + (size_t)B * L_DIM;           // [B, 384]

    convert_A<<<(int)(((size_t)B * H_DIM / 8) / 256), 256>>>(cls);
    transpose_w_h<<<dim3(H_DIM / 32, D_DIM / 32), dim3(32, 8)>>>(Wm);
    convert_Y<<<1, 128>>>(Y);
    gemm1_mma<<<dim3(D_DIM / 128, B / 128), 256, SMEM_TOTAL>>>(bias, x);
    expmap_warp<<<B / 8, 256>>>(x);
    gemm2_mma<<<B / 128, 256, SMEM_TOTAL>>>(logits);
}

// round 6
// speedup vs baseline: 2.3966x; 2.3966x over previous
#include <cuda_runtime.h>
#include <cuda_fp16.h>
#include <math.h>
#include <cstdint>

#define H_DIM 768
#define D_DIM 384
#define L_DIM 128
#define B_MAX 32768

// -------- scratch (module globals; no runtime allocation) --------
__device__ float  g_x2[B_MAX];
__device__ float  g_y2[L_DIM];
__device__ __half g_Ah[(size_t)B_MAX * H_DIM];   // cls in fp16
__device__ __half g_Xh[(size_t)B_MAX * D_DIM];   // x in fp16
__device__ __half g_Wth[(size_t)D_DIM * H_DIM];  // W^T in fp16 [D][H]
__device__ __half g_Yh[(size_t)L_DIM * D_DIM];   // Y in fp16 [L][D]

// ---------------- helpers ----------------
__device__ __forceinline__ uint32_t smem_u32(const void* p) {
    uint32_t a;
    asm("{ .reg .u64 t; cvta.to.shared.u64 t, %1; cvt.u32.u64 %0, t; }" : "=r"(a) : "l"(p));
    return a;
}
__device__ __forceinline__ void cp_async16(uint32_t s, const void* g) {
    asm volatile("cp.async.cg.shared.global [%0], [%1], 16;" :: "r"(s), "l"(g));
}
#define CP_COMMIT asm volatile("cp.async.commit_group;" ::: "memory")
#define CP_WAIT3  asm volatile("cp.async.wait_group 3;" ::: "memory")

__device__ __forceinline__ void mma_fp16(float* d, const uint32_t* a, const uint32_t* b) {
    asm volatile(
        "mma.sync.aligned.m16n8k16.row.col.f32.f16.f16.f32 "
        "{%0,%1,%2,%3}, {%4,%5,%6,%7}, {%8,%9}, {%0,%1,%2,%3};"
        : "+f"(d[0]), "+f"(d[1]), "+f"(d[2]), "+f"(d[3])
        : "r"(a[0]), "r"(a[1]), "r"(a[2]), "r"(a[3]), "r"(b[0]), "r"(b[1]));
}

#define ASTR_H 40                         // 32 k-halves + 8 pad (80B rows, conflict-free)
#define A_HALVES (256 * ASTR_H)           // 256x32 A tile
#define STAGE_HALVES (A_HALVES + 128 * ASTR_H)   // + 128x32 B tile
#define STAGE_BYTES  (STAGE_HALVES * 2)   // 30720
#define NSTAGE 4
#define SMEM_TOTAL   (NSTAGE * STAGE_BYTES)      // 122880

// one chunk (256x32 A + 128x32 B) with 512 threads
__device__ __forceinline__ void stage512(uint32_t sstage, const __half* Ag,
                                         const __half* Bg, int ld, int tid) {
#pragma unroll
    for (int i = 0; i < 2; ++i) {
        int idx = i * 512 + tid;
        int row = idx >> 2, k8 = idx & 3;
        cp_async16(sstage + (uint32_t)((row * ASTR_H + k8 * 8) * 2),
                   Ag + (size_t)row * ld + k8 * 8);
    }
    {
        int row = tid >> 2, k8 = tid & 3;
        cp_async16(sstage + (uint32_t)((A_HALVES + row * ASTR_H + k8 * 8) * 2),
                   Bg + (size_t)row * ld + k8 * 8);
    }
}

// one k16 step: load frags + 16 mmas (warp tile 64x32)
__device__ __forceinline__ void compute_k16(const __half* As, const __half* Bs,
                                            int kb, int wm, int wn, int lane,
                                            float acc[4][4][4]) {
    const int q2 = (lane & 3) * 2;
    uint32_t af[4][4];
#pragma unroll
    for (int mt = 0; mt < 4; ++mt) {
        int r = wm + mt * 16 + (lane >> 2);
        af[mt][0] = *(const uint32_t*)(As + r * ASTR_H + kb + q2);
        af[mt][1] = *(const uint32_t*)(As + (r + 8) * ASTR_H + kb + q2);
        af[mt][2] = *(const uint32_t*)(As + r * ASTR_H + kb + 8 + q2);
        af[mt][3] = *(const uint32_t*)(As + (r + 8) * ASTR_H + kb + 8 + q2);
    }
    uint32_t bf[4][2];
#pragma unroll
    for (int nt = 0; nt < 4; ++nt) {
        int n = wn + nt * 8 + (lane >> 2);
        bf[nt][0] = *(const uint32_t*)(Bs + n * ASTR_H + kb + q2);
        bf[nt][1] = *(const uint32_t*)(Bs + n * ASTR_H + kb + 8 + q2);
    }
#pragma unroll
    for (int mt = 0; mt < 4; ++mt)
#pragma unroll
        for (int nt = 0; nt < 4; ++nt)
            mma_fp16(acc[mt][nt], af[mt], bf[nt]);
}

// ---------------- conversion kernels ----------------
__global__ void convert_A(const float* __restrict__ A) {
    size_t i = (size_t)blockIdx.x * blockDim.x + threadIdx.x;   // one per 8 floats
    const float4 v0 = ((const float4*)A)[i * 2];
    const float4 v1 = ((const float4*)A)[i * 2 + 1];
    __half2 h0 = __floats2half2_rn(v0.x, v0.y);
    __half2 h1 = __floats2half2_rn(v0.z, v0.w);
    __half2 h2 = __floats2half2_rn(v1.x, v1.y);
    __half2 h3 = __floats2half2_rn(v1.z, v1.w);
    uint4 u;
    u.x = *(uint32_t*)&h0; u.y = *(uint32_t*)&h1;
    u.z = *(uint32_t*)&h2; u.w = *(uint32_t*)&h3;
    ((uint4*)g_Ah)[i] = u;
}

__global__ void transpose_w_h(const float* __restrict__ W) {
    __shared__ float t[32][33];
    int bx = blockIdx.x * 32;  // H dim
    int by = blockIdx.y * 32;  // D dim
    int x = threadIdx.x, y = threadIdx.y;   // 32 x 8
#pragma unroll
    for (int i = 0; i < 32; i += 8)
        t[y + i][x] = W[(size_t)(bx + y + i) * D_DIM + by + x];
    __syncthreads();
#pragma unroll
    for (int i = 0; i < 32; i += 8)
        g_Wth[(size_t)(by + y + i) * H_DIM + bx + x] = __float2half_rn(t[x][y + i]);
}

// warp per row: convert Y to fp16 + y2
__global__ __launch_bounds__(256)
void convert_Y(const float* __restrict__ Y) {
    const int warp = threadIdx.x >> 5, lane = threadIdx.x & 31;
    const int row = blockIdx.x * 8 + warp;
    const float* y = Y + (size_t)row * D_DIM;
    __half* yh = g_Yh + (size_t)row * D_DIM;
    float s = 0.f;
#pragma unroll
    for (int j = 0; j < 3; ++j) {
        float4 v = ((const float4*)y)[j * 32 + lane];
        s += v.x * v.x + v.y * v.y + v.z * v.z + v.w * v.w;
        __half2 h0 = __floats2half2_rn(v.x, v.y);
        __half2 h1 = __floats2half2_rn(v.z, v.w);
        uint2 u; u.x = *(uint32_t*)&h0; u.y = *(uint32_t*)&h1;
        ((uint2*)yh)[j * 32 + lane] = u;
    }
#pragma unroll
    for (int o = 16; o > 0; o >>= 1) s += __shfl_xor_sync(0xFFFFFFFFu, s, o);
    if (lane == 0) g_y2[row] = s;
}

// ---------------- expmap0: warp per row ----------------
__global__ __launch_bounds__(256)
void expmap_warp(float* __restrict__ P) {
    const int warp = threadIdx.x >> 5, lane = threadIdx.x & 31;
    const int row = blockIdx.x * 8 + warp;
    float* p = P + (size_t)row * D_DIM;
    __half* xh = g_Xh + (size_t)row * D_DIM;

    float4 v[3];
    float s = 0.f;
#pragma unroll
    for (int j = 0; j < 3; ++j) {
        v[j] = ((const float4*)p)[j * 32 + lane];
        s += v[j].x * v[j].x + v[j].y * v[j].y + v[j].z * v[j].z + v[j].w * v[j].w;
    }
#pragma unroll
    for (int o = 16; o > 0; o >>= 1) s += __shfl_xor_sync(0xFFFFFFFFu, s, o);

    float nsq = s;
    float n = fmaxf(sqrtf(nsq), 1e-15f);
    float scale = tanhf(n) / n;
    if (lane == 0) g_x2[row] = nsq * scale * scale;

#pragma unroll
    for (int j = 0; j < 3; ++j) {
        float4 w = v[j];
        w.x *= scale; w.y *= scale; w.z *= scale; w.w *= scale;
        ((float4*)p)[j * 32 + lane] = w;
        __half2 h0 = __floats2half2_rn(w.x, w.y);
        __half2 h1 = __floats2half2_rn(w.z, w.w);
        uint2 u; u.x = *(uint32_t*)&h0; u.y = *(uint32_t*)&h1;
        ((uint2*)xh)[j * 32 + lane] = u;
    }
}

// ---------------- GEMM1: projected = cls @ W + b (fp16 MMA, 256x128 tile) ----
__global__ __launch_bounds__(512, 1)
void gemm1_mma(const float* __restrict__ bias, float* __restrict__ P)
{
    extern __shared__ __half smh[];
    const uint32_t sb = smem_u32(smh);
    const int tid = threadIdx.x, lane = tid & 31, warp = tid >> 5;
    const int wm = (warp >> 2) * 64, wn = (warp & 3) * 32;
    const int rowBase = blockIdx.y * 256, colBase = blockIdx.x * 128;

    const __half* Abase = g_Ah + (size_t)rowBase * H_DIM;
    const __half* Bbase = g_Wth + (size_t)colBase * H_DIM;

    float acc[4][4][4];
#pragma unroll
    for (int mt = 0; mt < 4; ++mt)
#pragma unroll
        for (int nt = 0; nt < 4; ++nt)
#pragma unroll
            for (int q = 0; q < 4; ++q) acc[mt][nt][q] = 0.f;

    const int NCH = H_DIM / 32;   // 24
#pragma unroll
    for (int s = 0; s < NSTAGE - 1; ++s) {
        stage512(sb + s * STAGE_BYTES, Abase + s * 32, Bbase + s * 32, H_DIM, tid);
        CP_COMMIT;
    }

    for (int c = 0; c < NCH; ++c) {
        if (c + NSTAGE - 1 < NCH) {
            stage512(sb + ((c + NSTAGE - 1) % NSTAGE) * STAGE_BYTES,
                     Abase + (c + NSTAGE - 1) * 32, Bbase + (c + NSTAGE - 1) * 32, H_DIM, tid);
        }
        CP_COMMIT;
        CP_WAIT3;
        __syncthreads();
        const __half* As = smh + (c % NSTAGE) * STAGE_HALVES;
        const __half* Bs = As + A_HALVES;
        compute_k16(As, Bs, 0,  wm, wn, lane, acc);
        compute_k16(As, Bs, 16, wm, wn, lane, acc);
        __syncthreads();
    }

#pragma unroll
    for (int mt = 0; mt < 4; ++mt) {
        int r0 = rowBase + wm + mt * 16 + (lane >> 2);
#pragma unroll
        for (int nt = 0; nt < 4; ++nt) {
            int cc = colBase + wn + nt * 8 + (lane & 3) * 2;
            float b0 = bias[cc], b1 = bias[cc + 1];
            *(float2*)&P[(size_t)r0 * D_DIM + cc] =
                make_float2(acc[mt][nt][0] + b0, acc[mt][nt][1] + b1);
            *(float2*)&P[(size_t)(r0 + 8) * D_DIM + cc] =
                make_float2(acc[mt][nt][2] + b0, acc[mt][nt][3] + b1);
        }
    }
}

// ---------------- GEMM2: xy = x @ Y^T, fused Poincare distance -------------
__global__ __launch_bounds__(512, 1)
void gemm2_mma(float* __restrict__ logits)
{
    extern __shared__ __half smh[];
    const uint32_t sb = smem_u32(smh);
    const int tid = threadIdx.x, lane = tid & 31, warp = tid >> 5;
    const int wm = (warp >> 2) * 64, wn = (warp & 3) * 32;
    const int rowBase = blockIdx.x * 256;

    const __half* Abase = g_Xh + (size_t)rowBase * D_DIM;
    const __half* Bbase = g_Yh;

    float acc[4][4][4];
#pragma unroll
    for (int mt = 0; mt < 4; ++mt)
#pragma unroll
        for (int nt = 0; nt < 4; ++nt)
#pragma unroll
            for (int q = 0; q < 4; ++q) acc[mt][nt][q] = 0.f;

    const int NCH = D_DIM / 32;   // 12
#pragma unroll
    for (int s = 0; s < NSTAGE - 1; ++s) {
        stage512(sb + s * STAGE_BYTES, Abase + s * 32, Bbase + s * 32, D_DIM, tid);
        CP_COMMIT;
    }

    for (int c = 0; c < NCH; ++c) {
        if (c + NSTAGE - 1 < NCH) {
            stage512(sb + ((c + NSTAGE - 1) % NSTAGE) * STAGE_BYTES,
                     Abase + (c + NSTAGE - 1) * 32, Bbase + (c + NSTAGE - 1) * 32, D_DIM, tid);
        }
        CP_COMMIT;
        CP_WAIT3;
        __syncthreads();
        const __half* As = smh + (c % NSTAGE) * STAGE_HALVES;
        const __half* Bs = As + A_HALVES;
        compute_k16(As, Bs, 0,  wm, wn, lane, acc);
        compute_k16(As, Bs, 16, wm, wn, lane, acc);
        __syncthreads();
    }

    // ---- fused distance epilogue; common (clipped) path has NO MUFU ops ----
    const float CLIPMAX = (1.0f - 1e-5f) * (1.0f - 1e-5f);
    const float sclip = sqrtf(CLIPMAX);
    const float dclip = -__logf(__fdividef(1.0f + sclip, 1.0f - sclip)); // = -2*atanh(sclip)

#pragma unroll
    for (int mt = 0; mt < 4; ++mt) {
        int r0 = rowBase + wm + mt * 16 + (lane >> 2);
        float x2a = g_x2[r0];
        float x2b = g_x2[r0 + 8];
#pragma unroll
        for (int nt = 0; nt < 4; ++nt) {
            int cc = wn + nt * 8 + (lane & 3) * 2;
            float y2a = g_y2[cc], y2b = g_y2[cc + 1];
            float o[4];
#pragma unroll
            for (int q = 0; q < 4; ++q) {
                float xy = acc[mt][nt][q];
                float x2 = (q < 2) ? x2a : x2b;
                float y2 = (q & 1) ? y2b : y2a;
                float sq  = x2 + y2 - 2.0f * xy;
                float den = fmaf(x2, y2, 1.0f - 2.0f * xy);   // > 0 always
                if (sq >= CLIPMAX * den) {
                    o[q] = dclip;                              // ratio clipped high
                } else if (sq <= 0.0f) {
                    o[q] = 0.0f;                               // ratio clipped low
                } else {
                    float s = sqrtf(__fdividef(sq, den));
                    o[q] = -__logf(__fdividef(1.0f + s, 1.0f - s));
                }
            }
            *(float2*)&logits[(size_t)r0 * L_DIM + cc]       = make_float2(o[0], o[1]);
            *(float2*)&logits[(size_t)(r0 + 8) * L_DIM + cc] = make_float2(o[2], o[3]);
        }
    }
}

// ---------------------------------------------------------------------------
extern "C" void kernel_launch(void* const* d_in, const int* in_sizes, int n_in,
                              void* d_out, int out_size)
{
    const float* cls  = (const float*)d_in[0];   // [B, 768]
    const float* Wm   = (const float*)d_in[1];   // [768, 384]
    const float* bias = (const float*)d_in[2];   // [384]
    const float* Y    = (const float*)d_in[3];   // [128, 384]

    const int B = in_sizes[0] / H_DIM;

    float* out = (float*)d_out;
    float* logits = out;                          // [B, 128]
    float* x = out + (size_t)B * L_DIM;           // [B, 384]

    cudaFuncSetAttribute(gemm1_mma, cudaFuncAttributeMaxDynamicSharedMemorySize, SMEM_TOTAL);
    cudaFuncSetAttribute(gemm2_mma, cudaFuncAttributeMaxDynamicSharedMemorySize, SMEM_TOTAL);

    convert_A<<<(int)(((size_t)B * H_DIM / 8) / 256), 256>>>(cls);
    transpose_w_h<<<dim3(H_DIM / 32, D_DIM / 32), dim3(32, 8)>>>(Wm);
    convert_Y<<<L_DIM / 8, 256>>>(Y);
    gemm1_mma<<<dim3(D_DIM / 128, B / 256), 512, SMEM_TOTAL>>>(bias, x);
    expmap_warp<<<B / 8, 256>>>(x);
    gemm2_mma<<<B / 256, 512, SMEM_TOTAL>>>(logits);
}

// round 8
// speedup vs baseline: 2.7842x; 1.1617x over previous
#include <cuda_runtime.h>
#include <cuda_fp16.h>
#include <math.h>
#include <cstdint>

#define H_DIM 768
#define D_DIM 384
#define L_DIM 128
#define B_MAX 32768

// -------- scratch (module globals; no runtime allocation) --------
__device__ float  g_x2[B_MAX];
__device__ float  g_y2[L_DIM];
__device__ __half g_Ah[(size_t)B_MAX * H_DIM];   // cls in fp16
__device__ __half g_Xh[(size_t)B_MAX * D_DIM];   // x in fp16
__device__ __half g_Wth[(size_t)D_DIM * H_DIM];  // W^T in fp16 [D][H]
__device__ __half g_Yh[(size_t)L_DIM * D_DIM];   // Y in fp16 [L][D]

// ---------------- helpers ----------------
__device__ __forceinline__ uint32_t smem_u32(const void* p) {
    uint32_t a;
    asm("{ .reg .u64 t; cvta.to.shared.u64 t, %1; cvt.u32.u64 %0, t; }" : "=r"(a) : "l"(p));
    return a;
}
__device__ __forceinline__ void cp_async16(uint32_t s, const void* g) {
    asm volatile("cp.async.cg.shared.global [%0], [%1], 16;" :: "r"(s), "l"(g));
}
#define CP_COMMIT asm volatile("cp.async.commit_group;" ::: "memory")
#define CP_WAIT2  asm volatile("cp.async.wait_group 2;" ::: "memory")

__device__ __forceinline__ void mma_fp16(float* d, const uint32_t* a, const uint32_t* b) {
    asm volatile(
        "mma.sync.aligned.m16n8k16.row.col.f32.f16.f16.f32 "
        "{%0,%1,%2,%3}, {%4,%5,%6,%7}, {%8,%9}, {%0,%1,%2,%3};"
        : "+f"(d[0]), "+f"(d[1]), "+f"(d[2]), "+f"(d[3])
        : "r"(a[0]), "r"(a[1]), "r"(a[2]), "r"(a[3]), "r"(b[0]), "r"(b[1]));
}
__device__ __forceinline__ void ldsm_x4(uint32_t addr, uint32_t& r0, uint32_t& r1,
                                        uint32_t& r2, uint32_t& r3) {
    asm volatile("ldmatrix.sync.aligned.m8n8.x4.shared.b16 {%0,%1,%2,%3}, [%4];"
                 : "=r"(r0), "=r"(r1), "=r"(r2), "=r"(r3) : "r"(addr));
}

#define ASTR 72                             // 64 k-halves + 8 pad (144B rows)
#define A_HALVES (256 * ASTR)               // 256x64 A tile
#define A_BYTES  (A_HALVES * 2)             // 36864
#define STAGE_HALVES (A_HALVES + 128 * ASTR)
#define STAGE_BYTES  (STAGE_HALVES * 2)     // 55296
#define NSTAGE 3
#define SMEM_TOTAL   (NSTAGE * STAGE_BYTES) // 165888

// stage one k64 chunk: 256x64 A + 128x64 B, 512 threads
__device__ __forceinline__ void stage_k64(uint32_t sstage, const __half* Ag,
                                          const __half* Bg, int ld, int tid) {
#pragma unroll
    for (int i = 0; i < 4; ++i) {
        int idx = i * 512 + tid;
        int row = idx >> 3, k8 = idx & 7;
        cp_async16(sstage + (uint32_t)((row * ASTR + k8 * 8) * 2),
                   Ag + (size_t)row * ld + k8 * 8);
    }
#pragma unroll
    for (int i = 0; i < 2; ++i) {
        int idx = i * 512 + tid;
        int row = idx >> 3, k8 = idx & 7;
        cp_async16(sstage + (uint32_t)(A_BYTES + (row * ASTR + k8 * 8) * 2),
                   Bg + (size_t)row * ld + k8 * 8);
    }
}

// one k16 step via ldmatrix: 4 A-ldsm + 2 B-ldsm + 16 mma (warp tile 64x32)
__device__ __forceinline__ void compute_k16(uint32_t sA, uint32_t sB, int kb,
                                            int wm, int wn, int lane,
                                            float acc[4][4][4]) {
    const int il = lane & 7, g = lane >> 3;
    uint32_t af[4][4], bf[4][2];
    // A: groups -> [m0-7@kb][m8-15@kb][m0-7@kb+8][m8-15@kb+8]
    uint32_t aoff = (uint32_t)(((wm + (g & 1) * 8 + il) * ASTR + kb + (g >> 1) * 8) * 2);
#pragma unroll
    for (int mt = 0; mt < 4; ++mt)
        ldsm_x4(sA + aoff + mt * (16 * ASTR * 2),
                af[mt][0], af[mt][1], af[mt][2], af[mt][3]);
    // B: groups -> [n0-7@kb][n0-7@kb+8][n8-15@kb][n8-15@kb+8]
    uint32_t boff = (uint32_t)(((wn + (g >> 1) * 8 + il) * ASTR + kb + (g & 1) * 8) * 2);
#pragma unroll
    for (int np = 0; np < 2; ++np)
        ldsm_x4(sB + boff + np * (16 * ASTR * 2),
                bf[np * 2][0], bf[np * 2][1], bf[np * 2 + 1][0], bf[np * 2 + 1][1]);
#pragma unroll
    for (int mt = 0; mt < 4; ++mt)
#pragma unroll
        for (int nt = 0; nt < 4; ++nt)
            mma_fp16(acc[mt][nt], af[mt], bf[nt]);
}

// ---------------- conversion kernels ----------------
__global__ void convert_A(const float* __restrict__ A) {
    size_t i = (size_t)blockIdx.x * blockDim.x + threadIdx.x;   // one per 8 floats
    const float4 v0 = ((const float4*)A)[i * 2];
    const float4 v1 = ((const float4*)A)[i * 2 + 1];
    __half2 h0 = __floats2half2_rn(v0.x, v0.y);
    __half2 h1 = __floats2half2_rn(v0.z, v0.w);
    __half2 h2 = __floats2half2_rn(v1.x, v1.y);
    __half2 h3 = __floats2half2_rn(v1.z, v1.w);
    uint4 u;
    u.x = *(uint32_t*)&h0; u.y = *(uint32_t*)&h1;
    u.z = *(uint32_t*)&h2; u.w = *(uint32_t*)&h3;
    ((uint4*)g_Ah)[i] = u;
}

__global__ void transpose_w_h(const float* __restrict__ W) {
    __shared__ float t[32][33];
    int bx = blockIdx.x * 32;  // H dim
    int by = blockIdx.y * 32;  // D dim
    int x = threadIdx.x, y = threadIdx.y;   // 32 x 8
#pragma unroll
    for (int i = 0; i < 32; i += 8)
        t[y + i][x] = W[(size_t)(bx + y + i) * D_DIM + by + x];
    __syncthreads();
#pragma unroll
    for (int i = 0; i < 32; i += 8)
        g_Wth[(size_t)(by + y + i) * H_DIM + bx + x] = __float2half_rn(t[x][y + i]);
}

__global__ __launch_bounds__(256)
void convert_Y(const float* __restrict__ Y) {
    const int warp = threadIdx.x >> 5, lane = threadIdx.x & 31;
    const int row = blockIdx.x * 8 + warp;
    const float* y = Y + (size_t)row * D_DIM;
    __half* yh = g_Yh + (size_t)row * D_DIM;
    float s = 0.f;
#pragma unroll
    for (int j = 0; j < 3; ++j) {
        float4 v = ((const float4*)y)[j * 32 + lane];
        s += v.x * v.x + v.y * v.y + v.z * v.z + v.w * v.w;
        __half2 h0 = __floats2half2_rn(v.x, v.y);
        __half2 h1 = __floats2half2_rn(v.z, v.w);
        uint2 u; u.x = *(uint32_t*)&h0; u.y = *(uint32_t*)&h1;
        ((uint2*)yh)[j * 32 + lane] = u;
    }
#pragma unroll
    for (int o = 16; o > 0; o >>= 1) s += __shfl_xor_sync(0xFFFFFFFFu, s, o);
    if (lane == 0) g_y2[row] = s;
}

// ---------------- expmap0: warp per row ----------------
__global__ __launch_bounds__(256)
void expmap_warp(float* __restrict__ P) {
    const int warp = threadIdx.x >> 5, lane = threadIdx.x & 31;
    const int row = blockIdx.x * 8 + warp;
    float* p = P + (size_t)row * D_DIM;
    __half* xh = g_Xh + (size_t)row * D_DIM;

    float4 v[3];
    float s = 0.f;
#pragma unroll
    for (int j = 0; j < 3; ++j) {
        v[j] = ((const float4*)p)[j * 32 + lane];
        s += v[j].x * v[j].x + v[j].y * v[j].y + v[j].z * v[j].z + v[j].w * v[j].w;
    }
#pragma unroll
    for (int o = 16; o > 0; o >>= 1) s += __shfl_xor_sync(0xFFFFFFFFu, s, o);

    float nsq = s;
    float n = fmaxf(sqrtf(nsq), 1e-15f);
    float scale = tanhf(n) / n;
    if (lane == 0) g_x2[row] = nsq * scale * scale;

#pragma unroll
    for (int j = 0; j < 3; ++j) {
        float4 w = v[j];
        w.x *= scale; w.y *= scale; w.z *= scale; w.w *= scale;
        ((float4*)p)[j * 32 + lane] = w;
        __half2 h0 = __floats2half2_rn(w.x, w.y);
        __half2 h1 = __floats2half2_rn(w.z, w.w);
        uint2 u; u.x = *(uint32_t*)&h0; u.y = *(uint32_t*)&h1;
        ((uint2*)xh)[j * 32 + lane] = u;
    }
}

// ---------------- GEMM1: projected = cls @ W + b (fp16 MMA, 256x128 tile) ----
__global__ __launch_bounds__(512, 1)
void gemm1_mma(const float* __restrict__ bias, float* __restrict__ P)
{
    extern __shared__ __half smh[];
    const uint32_t sb = smem_u32(smh);
    const int tid = threadIdx.x, lane = tid & 31, warp = tid >> 5;
    const int wm = (warp >> 2) * 64, wn = (warp & 3) * 32;
    const int rowBase = blockIdx.y * 256, colBase = blockIdx.x * 128;

    const __half* Abase = g_Ah + (size_t)rowBase * H_DIM;
    const __half* Bbase = g_Wth + (size_t)colBase * H_DIM;

    float acc[4][4][4];
#pragma unroll
    for (int mt = 0; mt < 4; ++mt)
#pragma unroll
        for (int nt = 0; nt < 4; ++nt)
#pragma unroll
            for (int q = 0; q < 4; ++q) acc[mt][nt][q] = 0.f;

    const int NCH = H_DIM / 64;   // 12
#pragma unroll
    for (int s = 0; s < NSTAGE - 1; ++s) {
        stage_k64(sb + s * STAGE_BYTES, Abase + s * 64, Bbase + s * 64, H_DIM, tid);
        CP_COMMIT;
    }

    for (int c = 0; c < NCH; ++c) {
        if (c + NSTAGE - 1 < NCH) {
            stage_k64(sb + ((c + NSTAGE - 1) % NSTAGE) * STAGE_BYTES,
                      Abase + (c + NSTAGE - 1) * 64, Bbase + (c + NSTAGE - 1) * 64,
                      H_DIM, tid);
        }
        CP_COMMIT;
        CP_WAIT2;
        __syncthreads();
        const uint32_t sA = sb + (c % NSTAGE) * STAGE_BYTES;
        const uint32_t sB = sA + A_BYTES;
#pragma unroll
        for (int ks = 0; ks < 4; ++ks)
            compute_k16(sA, sB, ks * 16, wm, wn, lane, acc);
        __syncthreads();
    }

#pragma unroll
    for (int mt = 0; mt < 4; ++mt) {
        int r0 = rowBase + wm + mt * 16 + (lane >> 2);
#pragma unroll
        for (int nt = 0; nt < 4; ++nt) {
            int cc = colBase + wn + nt * 8 + (lane & 3) * 2;
            float b0 = bias[cc], b1 = bias[cc + 1];
            *(float2*)&P[(size_t)r0 * D_DIM + cc] =
                make_float2(acc[mt][nt][0] + b0, acc[mt][nt][1] + b1);
            *(float2*)&P[(size_t)(r0 + 8) * D_DIM + cc] =
                make_float2(acc[mt][nt][2] + b0, acc[mt][nt][3] + b1);
        }
    }
}

// ---------------- GEMM2: xy = x @ Y^T, fused Poincare distance -------------
__global__ __launch_bounds__(512, 1)
void gemm2_mma(float* __restrict__ logits)
{
    extern __shared__ __half smh[];
    const uint32_t sb = smem_u32(smh);
    const int tid = threadIdx.x, lane = tid & 31, warp = tid >> 5;
    const int wm = (warp >> 2) * 64, wn = (warp & 3) * 32;
    const int rowBase = blockIdx.x * 256;

    const __half* Abase = g_Xh + (size_t)rowBase * D_DIM;
    const __half* Bbase = g_Yh;

    float acc[4][4][4];
#pragma unroll
    for (int mt = 0; mt < 4; ++mt)
#pragma unroll
        for (int nt = 0; nt < 4; ++nt)
#pragma unroll
            for (int q = 0; q < 4; ++q) acc[mt][nt][q] = 0.f;

    const int NCH = D_DIM / 64;   // 6
#pragma unroll
    for (int s = 0; s < NSTAGE - 1; ++s) {
        stage_k64(sb + s * STAGE_BYTES, Abase + s * 64, Bbase + s * 64, D_DIM, tid);
        CP_COMMIT;
    }

    for (int c = 0; c < NCH; ++c) {
        if (c + NSTAGE - 1 < NCH) {
            stage_k64(sb + ((c + NSTAGE - 1) % NSTAGE) * STAGE_BYTES,
                      Abase + (c + NSTAGE - 1) * 64, Bbase + (c + NSTAGE - 1) * 64,
                      D_DIM, tid);
        }
        CP_COMMIT;
        CP_WAIT2;
        __syncthreads();
        const uint32_t sA = sb + (c % NSTAGE) * STAGE_BYTES;
        const uint32_t sB = sA + A_BYTES;
#pragma unroll
        for (int ks = 0; ks < 4; ++ks)
            compute_k16(sA, sB, ks * 16, wm, wn, lane, acc);
        __syncthreads();
    }

    // ---- fused distance epilogue; common (clipped) path has NO MUFU ops ----
    const float CLIPMAX = (1.0f - 1e-5f) * (1.0f - 1e-5f);
    const float sclip = sqrtf(CLIPMAX);
    const float dclip = -__logf(__fdividef(1.0f + sclip, 1.0f - sclip)); // = -2*atanh(sclip)

#pragma unroll
    for (int mt = 0; mt < 4; ++mt) {
        int r0 = rowBase + wm + mt * 16 + (lane >> 2);
        float x2a = g_x2[r0];
        float x2b = g_x2[r0 + 8];
#pragma unroll
        for (int nt = 0; nt < 4; ++nt) {
            int cc = wn + nt * 8 + (lane & 3) * 2;
            float y2a = g_y2[cc], y2b = g_y2[cc + 1];
            float o[4];
#pragma unroll
            for (int q = 0; q < 4; ++q) {
                float xy = acc[mt][nt][q];
                float x2 = (q < 2) ? x2a : x2b;
                float y2 = (q & 1) ? y2b : y2a;
                float sq  = x2 + y2 - 2.0f * xy;
                float den = fmaf(x2, y2, 1.0f - 2.0f * xy);   // > 0 always
                if (sq >= CLIPMAX * den) {
                    o[q] = dclip;                              // ratio clipped high
                } else if (sq <= 0.0f) {
                    o[q] = 0.0f;                               // ratio clipped low
                } else {
                    float s = sqrtf(__fdividef(sq, den));
                    o[q] = -__logf(__fdividef(1.0f + s, 1.0f - s));
                }
            }
            *(float2*)&logits[(size_t)r0 * L_DIM + cc]       = make_float2(o[0], o[1]);
            *(float2*)&logits[(size_t)(r0 + 8) * L_DIM + cc] = make_float2(o[2], o[3]);
        }
    }
}

// ---------------------------------------------------------------------------
extern "C" void kernel_launch(void* const* d_in, const int* in_sizes, int n_in,
                              void* d_out, int out_size)
{
    const float* cls  = (const float*)d_in[0];   // [B, 768]
    const float* Wm   = (const float*)d_in[1];   // [768, 384]
    const float* bias = (const float*)d_in[2];   // [384]
    const float* Y    = (const float*)d_in[3];   // [128, 384]

    const int B = in_sizes[0] / H_DIM;

    float* out = (float*)d_out;
    float* logits = out;                          // [B, 128]
    float* x = out + (size_t)B * L_DIM;           // [B, 384]

    cudaFuncSetAttribute(gemm1_mma, cudaFuncAttributeMaxDynamicSharedMemorySize, SMEM_TOTAL);
    cudaFuncSetAttribute(gemm2_mma, cudaFuncAttributeMaxDynamicSharedMemorySize, SMEM_TOTAL);

    convert_A<<<(int)(((size_t)B * H_DIM / 8) / 256), 256>>>(cls);
    transpose_w_h<<<dim3(H_DIM / 32, D_DIM / 32), dim3(32, 8)>>>(Wm);
    convert_Y<<<L_DIM / 8, 256>>>(Y);
    gemm1_mma<<<dim3(D_DIM / 128, B / 256), 512, SMEM_TOTAL>>>(bias, x);
    expmap_warp<<<B / 8, 256>>>(x);
    gemm2_mma<<<B / 256, 512, SMEM_TOTAL>>>(logits);
}

// round 9
// speedup vs baseline: 2.8162x; 1.0115x over previous
#include <cuda_runtime.h>
#include <cuda_fp16.h>
#include <math.h>
#include <cstdint>

#define H_DIM 768
#define D_DIM 384
#define L_DIM 128
#define B_MAX 32768

// -------- scratch (module globals; no runtime allocation) --------
__device__ float  g_x2[B_MAX];
__device__ float  g_y2[L_DIM];
__device__ __half g_Ah[(size_t)B_MAX * H_DIM];   // cls in fp16
__device__ __half g_Xh[(size_t)B_MAX * D_DIM];   // x in fp16
__device__ __half g_Wth[(size_t)D_DIM * H_DIM];  // W^T in fp16 [D][H]
__device__ __half g_Yh[(size_t)L_DIM * D_DIM];   // Y in fp16 [L][D]

// ---------------- helpers ----------------
__device__ __forceinline__ uint32_t smem_u32(const void* p) {
    uint32_t a;
    asm("{ .reg .u64 t; cvta.to.shared.u64 t, %1; cvt.u32.u64 %0, t; }" : "=r"(a) : "l"(p));
    return a;
}
__device__ __forceinline__ void cp_async16(uint32_t s, const void* g) {
    asm volatile("cp.async.cg.shared.global [%0], [%1], 16;" :: "r"(s), "l"(g));
}
#define CP_COMMIT asm volatile("cp.async.commit_group;" ::: "memory")
#define CP_WAIT1  asm volatile("cp.async.wait_group 1;" ::: "memory")
#define CP_WAIT0  asm volatile("cp.async.wait_group 0;" ::: "memory")

__device__ __forceinline__ void mma_fp16(float* d, const uint32_t* a, const uint32_t* b) {
    asm volatile(
        "mma.sync.aligned.m16n8k16.row.col.f32.f16.f16.f32 "
        "{%0,%1,%2,%3}, {%4,%5,%6,%7}, {%8,%9}, {%0,%1,%2,%3};"
        : "+f"(d[0]), "+f"(d[1]), "+f"(d[2]), "+f"(d[3])
        : "r"(a[0]), "r"(a[1]), "r"(a[2]), "r"(a[3]), "r"(b[0]), "r"(b[1]));
}
__device__ __forceinline__ void ldsm_x4(uint32_t addr, uint32_t& r0, uint32_t& r1,
                                        uint32_t& r2, uint32_t& r3) {
    asm volatile("ldmatrix.sync.aligned.m8n8.x4.shared.b16 {%0,%1,%2,%3}, [%4];"
                 : "=r"(r0), "=r"(r1), "=r"(r2), "=r"(r3) : "r"(addr));
}

#define ASTR 136                            // 128 k-halves + 8 pad (272B rows, LDSM conflict-free)
#define A_HALVES (256 * ASTR)               // 256x128 A tile
#define A_BYTES  (A_HALVES * 2)             // 69632
#define STAGE_HALVES (A_HALVES + 128 * ASTR)
#define STAGE_BYTES  (STAGE_HALVES * 2)     // 104448
#define SMEM_TOTAL   (2 * STAGE_BYTES)      // 208896

// stage one k128 chunk: 256x128 A + 128x128 B (fp16), 512 threads
__device__ __forceinline__ void stage_k128(uint32_t sstage, const __half* Ag,
                                           const __half* Bg, int ld, int tid) {
#pragma unroll
    for (int i = 0; i < 8; ++i) {
        int idx = i * 512 + tid;
        int row = idx >> 4, k8 = idx & 15;
        cp_async16(sstage + (uint32_t)((row * ASTR + k8 * 8) * 2),
                   Ag + (size_t)row * ld + k8 * 8);
    }
#pragma unroll
    for (int i = 0; i < 4; ++i) {
        int idx = i * 512 + tid;
        int row = idx >> 4, k8 = idx & 15;
        cp_async16(sstage + (uint32_t)(A_BYTES + (row * ASTR + k8 * 8) * 2),
                   Bg + (size_t)row * ld + k8 * 8);
    }
}

// load fragments for one k16 step (no mma)
__device__ __forceinline__ void load_frags(uint32_t sA, uint32_t sB, int kb,
                                           int wm, int wn, int lane,
                                           uint32_t af[4][4], uint32_t bf[4][2]) {
    const int il = lane & 7, g = lane >> 3;
    uint32_t aoff = (uint32_t)(((wm + (g & 1) * 8 + il) * ASTR + kb + (g >> 1) * 8) * 2);
#pragma unroll
    for (int mt = 0; mt < 4; ++mt)
        ldsm_x4(sA + aoff + mt * (16 * ASTR * 2),
                af[mt][0], af[mt][1], af[mt][2], af[mt][3]);
    uint32_t boff = (uint32_t)(((wn + (g >> 1) * 8 + il) * ASTR + kb + (g & 1) * 8) * 2);
#pragma unroll
    for (int np = 0; np < 2; ++np)
        ldsm_x4(sB + boff + np * (16 * ASTR * 2),
                bf[np * 2][0], bf[np * 2][1], bf[np * 2 + 1][0], bf[np * 2 + 1][1]);
}
__device__ __forceinline__ void mma_all(uint32_t af[4][4], uint32_t bf[4][2],
                                        float acc[4][4][4]) {
#pragma unroll
    for (int mt = 0; mt < 4; ++mt)
#pragma unroll
        for (int nt = 0; nt < 4; ++nt)
            mma_fp16(acc[mt][nt], af[mt], bf[nt]);
}

// one k128 chunk: 8 k16 steps, fragment double-buffered
__device__ __forceinline__ void compute_chunk(uint32_t sA, uint32_t sB,
                                              int wm, int wn, int lane,
                                              float acc[4][4][4]) {
    uint32_t af[2][4][4], bf[2][4][2];
    load_frags(sA, sB, 0, wm, wn, lane, af[0], bf[0]);
#pragma unroll
    for (int s = 0; s < 8; ++s) {
        if (s < 7)
            load_frags(sA, sB, (s + 1) * 16, wm, wn, lane, af[(s + 1) & 1], bf[(s + 1) & 1]);
        mma_all(af[s & 1], bf[s & 1], acc);
    }
}

// ---------------- conversion kernels ----------------
__global__ void convert_A(const float* __restrict__ A) {
    size_t i = (size_t)blockIdx.x * blockDim.x + threadIdx.x;   // one per 8 floats
    const float4 v0 = ((const float4*)A)[i * 2];
    const float4 v1 = ((const float4*)A)[i * 2 + 1];
    __half2 h0 = __floats2half2_rn(v0.x, v0.y);
    __half2 h1 = __floats2half2_rn(v0.z, v0.w);
    __half2 h2 = __floats2half2_rn(v1.x, v1.y);
    __half2 h3 = __floats2half2_rn(v1.z, v1.w);
    uint4 u;
    u.x = *(uint32_t*)&h0; u.y = *(uint32_t*)&h1;
    u.z = *(uint32_t*)&h2; u.w = *(uint32_t*)&h3;
    ((uint4*)g_Ah)[i] = u;
}

__global__ void transpose_w_h(const float* __restrict__ W) {
    __shared__ float t[32][33];
    int bx = blockIdx.x * 32;  // H dim
    int by = blockIdx.y * 32;  // D dim
    int x = threadIdx.x, y = threadIdx.y;   // 32 x 8
#pragma unroll
    for (int i = 0; i < 32; i += 8)
        t[y + i][x] = W[(size_t)(bx + y + i) * D_DIM + by + x];
    __syncthreads();
#pragma unroll
    for (int i = 0; i < 32; i += 8)
        g_Wth[(size_t)(by + y + i) * H_DIM + bx + x] = __float2half_rn(t[x][y + i]);
}

__global__ __launch_bounds__(256)
void convert_Y(const float* __restrict__ Y) {
    const int warp = threadIdx.x >> 5, lane = threadIdx.x & 31;
    const int row = blockIdx.x * 8 + warp;
    const float* y = Y + (size_t)row * D_DIM;
    __half* yh = g_Yh + (size_t)row * D_DIM;
    float s = 0.f;
#pragma unroll
    for (int j = 0; j < 3; ++j) {
        float4 v = ((const float4*)y)[j * 32 + lane];
        s += v.x * v.x + v.y * v.y + v.z * v.z + v.w * v.w;
        __half2 h0 = __floats2half2_rn(v.x, v.y);
        __half2 h1 = __floats2half2_rn(v.z, v.w);
        uint2 u; u.x = *(uint32_t*)&h0; u.y = *(uint32_t*)&h1;
        ((uint2*)yh)[j * 32 + lane] = u;
    }
#pragma unroll
    for (int o = 16; o > 0; o >>= 1) s += __shfl_xor_sync(0xFFFFFFFFu, s, o);
    if (lane == 0) g_y2[row] = s;
}

// ---------------- expmap0: warp per row ----------------
__global__ __launch_bounds__(256)
void expmap_warp(float* __restrict__ P) {
    const int warp = threadIdx.x >> 5, lane = threadIdx.x & 31;
    const int row = blockIdx.x * 8 + warp;
    float* p = P + (size_t)row * D_DIM;
    __half* xh = g_Xh + (size_t)row * D_DIM;

    float4 v[3];
    float s = 0.f;
#pragma unroll
    for (int j = 0; j < 3; ++j) {
        v[j] = ((const float4*)p)[j * 32 + lane];
        s += v[j].x * v[j].x + v[j].y * v[j].y + v[j].z * v[j].z + v[j].w * v[j].w;
    }
#pragma unroll
    for (int o = 16; o > 0; o >>= 1) s += __shfl_xor_sync(0xFFFFFFFFu, s, o);

    float nsq = s;
    float n = fmaxf(sqrtf(nsq), 1e-15f);
    float scale = tanhf(n) / n;
    if (lane == 0) g_x2[row] = nsq * scale * scale;

#pragma unroll
    for (int j = 0; j < 3; ++j) {
        float4 w = v[j];
        w.x *= scale; w.y *= scale; w.z *= scale; w.w *= scale;
        ((float4*)p)[j * 32 + lane] = w;
        __half2 h0 = __floats2half2_rn(w.x, w.y);
        __half2 h1 = __floats2half2_rn(w.z, w.w);
        uint2 u; u.x = *(uint32_t*)&h0; u.y = *(uint32_t*)&h1;
        ((uint2*)xh)[j * 32 + lane] = u;
    }
}

// ---------------- GEMM1: projected = cls @ W + b (fp16 MMA, 256x128 tile) ----
__global__ __launch_bounds__(512, 1)
void gemm1_mma(const float* __restrict__ bias, float* __restrict__ P)
{
    extern __shared__ __half smh[];
    const uint32_t sb = smem_u32(smh);
    const int tid = threadIdx.x, lane = tid & 31, warp = tid >> 5;
    const int wm = (warp >> 2) * 64, wn = (warp & 3) * 32;
    const int rowBase = blockIdx.y * 256, colBase = blockIdx.x * 128;

    const __half* Abase = g_Ah + (size_t)rowBase * H_DIM;
    const __half* Bbase = g_Wth + (size_t)colBase * H_DIM;

    float acc[4][4][4];
#pragma unroll
    for (int mt = 0; mt < 4; ++mt)
#pragma unroll
        for (int nt = 0; nt < 4; ++nt)
#pragma unroll
            for (int q = 0; q < 4; ++q) acc[mt][nt][q] = 0.f;

    const int NCH = H_DIM / 128;   // 6
    stage_k128(sb, Abase, Bbase, H_DIM, tid);
    CP_COMMIT;
    stage_k128(sb + STAGE_BYTES, Abase + 128, Bbase + 128, H_DIM, tid);
    CP_COMMIT;

#pragma unroll 1
    for (int c = 0; c < NCH; ++c) {
        if (c == NCH - 1) { CP_WAIT0; } else { CP_WAIT1; }
        __syncthreads();
        const uint32_t sA = sb + (c & 1) * STAGE_BYTES;
        compute_chunk(sA, sA + A_BYTES, wm, wn, lane, acc);
        if (c + 2 < NCH) {
            __syncthreads();
            stage_k128(sb + (c & 1) * STAGE_BYTES,
                       Abase + (c + 2) * 128, Bbase + (c + 2) * 128, H_DIM, tid);
            CP_COMMIT;
        }
    }

#pragma unroll
    for (int mt = 0; mt < 4; ++mt) {
        int r0 = rowBase + wm + mt * 16 + (lane >> 2);
#pragma unroll
        for (int nt = 0; nt < 4; ++nt) {
            int cc = colBase + wn + nt * 8 + (lane & 3) * 2;
            float b0 = bias[cc], b1 = bias[cc + 1];
            *(float2*)&P[(size_t)r0 * D_DIM + cc] =
                make_float2(acc[mt][nt][0] + b0, acc[mt][nt][1] + b1);
            *(float2*)&P[(size_t)(r0 + 8) * D_DIM + cc] =
                make_float2(acc[mt][nt][2] + b0, acc[mt][nt][3] + b1);
        }
    }
}

// ---------------- GEMM2: xy = x @ Y^T, fused Poincare distance -------------
__global__ __launch_bounds__(512, 1)
void gemm2_mma(float* __restrict__ logits)
{
    extern __shared__ __half smh[];
    const uint32_t sb = smem_u32(smh);
    const int tid = threadIdx.x, lane = tid & 31, warp = tid >> 5;
    const int wm = (warp >> 2) * 64, wn = (warp & 3) * 32;
    const int rowBase = blockIdx.x * 256;

    const __half* Abase = g_Xh + (size_t)rowBase * D_DIM;
    const __half* Bbase = g_Yh;

    float acc[4][4][4];
#pragma unroll
    for (int mt = 0; mt < 4; ++mt)
#pragma unroll
        for (int nt = 0; nt < 4; ++nt)
#pragma unroll
            for (int q = 0; q < 4; ++q) acc[mt][nt][q] = 0.f;

    const int NCH = D_DIM / 128;   // 3
    stage_k128(sb, Abase, Bbase, D_DIM, tid);
    CP_COMMIT;
    stage_k128(sb + STAGE_BYTES, Abase + 128, Bbase + 128, D_DIM, tid);
    CP_COMMIT;

#pragma unroll 1
    for (int c = 0; c < NCH; ++c) {
        if (c == NCH - 1) { CP_WAIT0; } else { CP_WAIT1; }
        __syncthreads();
        const uint32_t sA = sb + (c & 1) * STAGE_BYTES;
        compute_chunk(sA, sA + A_BYTES, wm, wn, lane, acc);
        if (c + 2 < NCH) {
            __syncthreads();
            stage_k128(sb + (c & 1) * STAGE_BYTES,
                       Abase + (c + 2) * 128, Bbase + (c + 2) * 128, D_DIM, tid);
            CP_COMMIT;
        }
    }

    // ---- fused distance epilogue; common (clipped) path has NO MUFU ops ----
    const float CLIPMAX = (1.0f - 1e-5f) * (1.0f - 1e-5f);
    const float sclip = sqrtf(CLIPMAX);
    const float dclip = -__logf(__fdividef(1.0f + sclip, 1.0f - sclip)); // = -2*atanh(sclip)

#pragma unroll
    for (int mt = 0; mt < 4; ++mt) {
        int r0 = rowBase + wm + mt * 16 + (lane >> 2);
        float x2a = g_x2[r0];
        float x2b = g_x2[r0 + 8];
#pragma unroll
        for (int nt = 0; nt < 4; ++nt) {
            int cc = wn + nt * 8 + (lane & 3) * 2;
            float y2a = g_y2[cc], y2b = g_y2[cc + 1];
            float o[4];
#pragma unroll
            for (int q = 0; q < 4; ++q) {
                float xy = acc[mt][nt][q];
                float x2 = (q < 2) ? x2a : x2b;
                float y2 = (q & 1) ? y2b : y2a;
                float sq  = x2 + y2 - 2.0f * xy;
                float den = fmaf(x2, y2, 1.0f - 2.0f * xy);   // > 0 always
                if (sq >= CLIPMAX * den) {
                    o[q] = dclip;                              // ratio clipped high
                } else if (sq <= 0.0f) {
                    o[q] = 0.0f;                               // ratio clipped low
                } else {
                    float s = sqrtf(__fdividef(sq, den));
                    o[q] = -__logf(__fdividef(1.0f + s, 1.0f - s));
                }
            }
            *(float2*)&logits[(size_t)r0 * L_DIM + cc]       = make_float2(o[0], o[1]);
            *(float2*)&logits[(size_t)(r0 + 8) * L_DIM + cc] = make_float2(o[2], o[3]);
        }
    }
}

// ---------------------------------------------------------------------------
extern "C" void kernel_launch(void* const* d_in, const int* in_sizes, int n_in,
                              void* d_out, int out_size)
{
    const float* cls  = (const float*)d_in[0];   // [B, 768]
    const float* Wm   = (const float*)d_in[1];   // [768, 384]
    const float* bias = (const float*)d_in[2];   // [384]
    const float* Y    = (const float*)d_in[3];   // [128, 384]

    const int B = in_sizes[0] / H_DIM;

    float* out = (float*)d_out;
    float* logits = out;                          // [B, 128]
    float* x = out + (size_t)B * L_DIM;           // [B, 384]

    cudaFuncSetAttribute(gemm1_mma, cudaFuncAttributeMaxDynamicSharedMemorySize, SMEM_TOTAL);
    cudaFuncSetAttribute(gemm2_mma, cudaFuncAttributeMaxDynamicSharedMemorySize, SMEM_TOTAL);

    convert_A<<<(int)(((size_t)B * H_DIM / 8) / 256), 256>>>(cls);
    transpose_w_h<<<dim3(H_DIM / 32, D_DIM / 32), dim3(32, 8)>>>(Wm);
    convert_Y<<<L_DIM / 8, 256>>>(Y);
    gemm1_mma<<<dim3(D_DIM / 128, B / 256), 512, SMEM_TOTAL>>>(bias, x);
    expmap_warp<<<B / 8, 256>>>(x);
    gemm2_mma<<<B / 256, 512, SMEM_TOTAL>>>(logits);
}

// round 10
// speedup vs baseline: 2.8369x; 1.0073x over previous
#include <cuda_runtime.h>
#include <cuda_fp16.h>
#include <math.h>
#include <cstdint>

#define H_DIM 768
#define D_DIM 384
#define L_DIM 128
#define B_MAX 32768

// -------- scratch (module globals; no runtime allocation) --------
__device__ float  g_x2[B_MAX];
__device__ float  g_y2[L_DIM];
__device__ __half g_Ah[(size_t)B_MAX * H_DIM];   // cls in fp16
__device__ __half g_Xh[(size_t)B_MAX * D_DIM];   // x in fp16
__device__ __half g_Wth[(size_t)D_DIM * H_DIM];  // W^T in fp16 [D][H]
__device__ __half g_Yh[(size_t)L_DIM * D_DIM];   // Y in fp16 [L][D]

// ---------------- helpers ----------------
__device__ __forceinline__ uint32_t smem_u32(const void* p) {
    uint32_t a;
    asm("{ .reg .u64 t; cvta.to.shared.u64 t, %1; cvt.u32.u64 %0, t; }" : "=r"(a) : "l"(p));
    return a;
}
__device__ __forceinline__ void cp_async16(uint32_t s, const void* g) {
    asm volatile("cp.async.cg.shared.global [%0], [%1], 16;" :: "r"(s), "l"(g));
}
#define CP_COMMIT asm volatile("cp.async.commit_group;" ::: "memory")
#define CP_WAIT2  asm volatile("cp.async.wait_group 2;" ::: "memory")

__device__ __forceinline__ void mma_fp16(float* d, const uint32_t* a, const uint32_t* b) {
    asm volatile(
        "mma.sync.aligned.m16n8k16.row.col.f32.f16.f16.f32 "
        "{%0,%1,%2,%3}, {%4,%5,%6,%7}, {%8,%9}, {%0,%1,%2,%3};"
        : "+f"(d[0]), "+f"(d[1]), "+f"(d[2]), "+f"(d[3])
        : "r"(a[0]), "r"(a[1]), "r"(a[2]), "r"(a[3]), "r"(b[0]), "r"(b[1]));
}
__device__ __forceinline__ void ldsm_x4(uint32_t addr, uint32_t& r0, uint32_t& r1,
                                        uint32_t& r2, uint32_t& r3) {
    asm volatile("ldmatrix.sync.aligned.m8n8.x4.shared.b16 {%0,%1,%2,%3}, [%4];"
                 : "=r"(r0), "=r"(r1), "=r"(r2), "=r"(r3) : "r"(addr));
}

#define ASTR 72                             // 64 k-halves + 8 pad (144B rows)
#define A_HALVES (128 * ASTR)               // 128x64 A tile
#define A_BYTES  (A_HALVES * 2)             // 18432
#define STAGE_HALVES (A_HALVES + 128 * ASTR)
#define STAGE_BYTES  (STAGE_HALVES * 2)     // 36864
#define NSTAGE 3
#define SMEM_TOTAL   (NSTAGE * STAGE_BYTES) // 110592 -> 2 CTAs/SM

// stage one k64 chunk: 128x64 A + 128x64 B (fp16), 256 threads
__device__ __forceinline__ void stage_k64(uint32_t sstage, const __half* Ag,
                                          const __half* Bg, int ld, int tid) {
#pragma unroll
    for (int i = 0; i < 4; ++i) {
        int idx = i * 256 + tid;
        int row = idx >> 3, k8 = idx & 7;
        cp_async16(sstage + (uint32_t)((row * ASTR + k8 * 8) * 2),
                   Ag + (size_t)row * ld + k8 * 8);
    }
#pragma unroll
    for (int i = 0; i < 4; ++i) {
        int idx = i * 256 + tid;
        int row = idx >> 3, k8 = idx & 7;
        cp_async16(sstage + (uint32_t)(A_BYTES + (row * ASTR + k8 * 8) * 2),
                   Bg + (size_t)row * ld + k8 * 8);
    }
}

// load fragments for one k16 step (no mma)
__device__ __forceinline__ void load_frags(uint32_t sA, uint32_t sB, int kb,
                                           int wm, int wn, int lane,
                                           uint32_t af[4][4], uint32_t bf[4][2]) {
    const int il = lane & 7, g = lane >> 3;
    uint32_t aoff = (uint32_t)(((wm + (g & 1) * 8 + il) * ASTR + kb + (g >> 1) * 8) * 2);
#pragma unroll
    for (int mt = 0; mt < 4; ++mt)
        ldsm_x4(sA + aoff + mt * (16 * ASTR * 2),
                af[mt][0], af[mt][1], af[mt][2], af[mt][3]);
    uint32_t boff = (uint32_t)(((wn + (g >> 1) * 8 + il) * ASTR + kb + (g & 1) * 8) * 2);
#pragma unroll
    for (int np = 0; np < 2; ++np)
        ldsm_x4(sB + boff + np * (16 * ASTR * 2),
                bf[np * 2][0], bf[np * 2][1], bf[np * 2 + 1][0], bf[np * 2 + 1][1]);
}
__device__ __forceinline__ void mma_all(uint32_t af[4][4], uint32_t bf[4][2],
                                        float acc[4][4][4]) {
#pragma unroll
    for (int mt = 0; mt < 4; ++mt)
#pragma unroll
        for (int nt = 0; nt < 4; ++nt)
            mma_fp16(acc[mt][nt], af[mt], bf[nt]);
}

// one k64 chunk: 4 k16 steps, fragment double-buffered
__device__ __forceinline__ void compute_chunk(uint32_t sA, uint32_t sB,
                                              int wm, int wn, int lane,
                                              float acc[4][4][4]) {
    uint32_t af[2][4][4], bf[2][4][2];
    load_frags(sA, sB, 0, wm, wn, lane, af[0], bf[0]);
#pragma unroll
    for (int s = 0; s < 4; ++s) {
        if (s < 3)
            load_frags(sA, sB, (s + 1) * 16, wm, wn, lane, af[(s + 1) & 1], bf[(s + 1) & 1]);
        mma_all(af[s & 1], bf[s & 1], acc);
    }
}

// ---------------- conversion kernels ----------------
__global__ void convert_A(const float* __restrict__ A) {
    size_t i = (size_t)blockIdx.x * blockDim.x + threadIdx.x;   // one per 8 floats
    const float4 v0 = ((const float4*)A)[i * 2];
    const float4 v1 = ((const float4*)A)[i * 2 + 1];
    __half2 h0 = __floats2half2_rn(v0.x, v0.y);
    __half2 h1 = __floats2half2_rn(v0.z, v0.w);
    __half2 h2 = __floats2half2_rn(v1.x, v1.y);
    __half2 h3 = __floats2half2_rn(v1.z, v1.w);
    uint4 u;
    u.x = *(uint32_t*)&h0; u.y = *(uint32_t*)&h1;
    u.z = *(uint32_t*)&h2; u.w = *(uint32_t*)&h3;
    ((uint4*)g_Ah)[i] = u;
}

__global__ void transpose_w_h(const float* __restrict__ W) {
    __shared__ float t[32][33];
    int bx = blockIdx.x * 32;  // H dim
    int by = blockIdx.y * 32;  // D dim
    int x = threadIdx.x, y = threadIdx.y;   // 32 x 8
#pragma unroll
    for (int i = 0; i < 32; i += 8)
        t[y + i][x] = W[(size_t)(bx + y + i) * D_DIM + by + x];
    __syncthreads();
#pragma unroll
    for (int i = 0; i < 32; i += 8)
        g_Wth[(size_t)(by + y + i) * H_DIM + bx + x] = __float2half_rn(t[x][y + i]);
}

__global__ __launch_bounds__(256)
void convert_Y(const float* __restrict__ Y) {
    const int warp = threadIdx.x >> 5, lane = threadIdx.x & 31;
    const int row = blockIdx.x * 8 + warp;
    const float* y = Y + (size_t)row * D_DIM;
    __half* yh = g_Yh + (size_t)row * D_DIM;
    float s = 0.f;
#pragma unroll
    for (int j = 0; j < 3; ++j) {
        float4 v = ((const float4*)y)[j * 32 + lane];
        s += v.x * v.x + v.y * v.y + v.z * v.z + v.w * v.w;
        __half2 h0 = __floats2half2_rn(v.x, v.y);
        __half2 h1 = __floats2half2_rn(v.z, v.w);
        uint2 u; u.x = *(uint32_t*)&h0; u.y = *(uint32_t*)&h1;
        ((uint2*)yh)[j * 32 + lane] = u;
    }
#pragma unroll
    for (int o = 16; o > 0; o >>= 1) s += __shfl_xor_sync(0xFFFFFFFFu, s, o);
    if (lane == 0) g_y2[row] = s;
}

// ---------------- expmap0: warp per row ----------------
__global__ __launch_bounds__(256)
void expmap_warp(float* __restrict__ P) {
    const int warp = threadIdx.x >> 5, lane = threadIdx.x & 31;
    const int row = blockIdx.x * 8 + warp;
    float* p = P + (size_t)row * D_DIM;
    __half* xh = g_Xh + (size_t)row * D_DIM;

    float4 v[3];
    float s = 0.f;
#pragma unroll
    for (int j = 0; j < 3; ++j) {
        v[j] = ((const float4*)p)[j * 32 + lane];
        s += v[j].x * v[j].x + v[j].y * v[j].y + v[j].z * v[j].z + v[j].w * v[j].w;
    }
#pragma unroll
    for (int o = 16; o > 0; o >>= 1) s += __shfl_xor_sync(0xFFFFFFFFu, s, o);

    float nsq = s;
    float n = fmaxf(sqrtf(nsq), 1e-15f);
    float scale = tanhf(n) / n;
    if (lane == 0) g_x2[row] = nsq * scale * scale;

#pragma unroll
    for (int j = 0; j < 3; ++j) {
        float4 w = v[j];
        w.x *= scale; w.y *= scale; w.z *= scale; w.w *= scale;
        ((float4*)p)[j * 32 + lane] = w;
        __half2 h0 = __floats2half2_rn(w.x, w.y);
        __half2 h1 = __floats2half2_rn(w.z, w.w);
        uint2 u; u.x = *(uint32_t*)&h0; u.y = *(uint32_t*)&h1;
        ((uint2*)xh)[j * 32 + lane] = u;
    }
}

// ---------------- GEMM1: projected = cls @ W + b (fp16 MMA, 128x128 tile) ----
__global__ __launch_bounds__(256, 2)
void gemm1_mma(const float* __restrict__ bias, float* __restrict__ P)
{
    extern __shared__ __half smh[];
    const uint32_t sb = smem_u32(smh);
    const int tid = threadIdx.x, lane = tid & 31, warp = tid >> 5;
    const int wm = (warp >> 2) * 64, wn = (warp & 3) * 32;
    const int rowBase = blockIdx.y * 128, colBase = blockIdx.x * 128;

    const __half* Abase = g_Ah + (size_t)rowBase * H_DIM;
    const __half* Bbase = g_Wth + (size_t)colBase * H_DIM;

    float acc[4][4][4];
#pragma unroll
    for (int mt = 0; mt < 4; ++mt)
#pragma unroll
        for (int nt = 0; nt < 4; ++nt)
#pragma unroll
            for (int q = 0; q < 4; ++q) acc[mt][nt][q] = 0.f;

    const int NCH = H_DIM / 64;   // 12
#pragma unroll
    for (int s = 0; s < NSTAGE - 1; ++s) {
        stage_k64(sb + s * STAGE_BYTES, Abase + s * 64, Bbase + s * 64, H_DIM, tid);
        CP_COMMIT;
    }

#pragma unroll 1
    for (int c = 0; c < NCH; ++c) {
        if (c + NSTAGE - 1 < NCH) {
            stage_k64(sb + ((c + NSTAGE - 1) % NSTAGE) * STAGE_BYTES,
                      Abase + (c + NSTAGE - 1) * 64, Bbase + (c + NSTAGE - 1) * 64,
                      H_DIM, tid);
        }
        CP_COMMIT;
        CP_WAIT2;
        __syncthreads();
        const uint32_t sA = sb + (c % NSTAGE) * STAGE_BYTES;
        compute_chunk(sA, sA + A_BYTES, wm, wn, lane, acc);
        __syncthreads();
    }

#pragma unroll
    for (int mt = 0; mt < 4; ++mt) {
        int r0 = rowBase + wm + mt * 16 + (lane >> 2);
#pragma unroll
        for (int nt = 0; nt < 4; ++nt) {
            int cc = colBase + wn + nt * 8 + (lane & 3) * 2;
            float b0 = bias[cc], b1 = bias[cc + 1];
            *(float2*)&P[(size_t)r0 * D_DIM + cc] =
                make_float2(acc[mt][nt][0] + b0, acc[mt][nt][1] + b1);
            *(float2*)&P[(size_t)(r0 + 8) * D_DIM + cc] =
                make_float2(acc[mt][nt][2] + b0, acc[mt][nt][3] + b1);
        }
    }
}

// ---------------- GEMM2: xy = x @ Y^T, fused Poincare distance -------------
__global__ __launch_bounds__(256, 2)
void gemm2_mma(float* __restrict__ logits)
{
    extern __shared__ __half smh[];
    const uint32_t sb = smem_u32(smh);
    const int tid = threadIdx.x, lane = tid & 31, warp = tid >> 5;
    const int wm = (warp >> 2) * 64, wn = (warp & 3) * 32;
    const int rowBase = blockIdx.x * 128;

    const __half* Abase = g_Xh + (size_t)rowBase * D_DIM;
    const __half* Bbase = g_Yh;

    float acc[4][4][4];
#pragma unroll
    for (int mt = 0; mt < 4; ++mt)
#pragma unroll
        for (int nt = 0; nt < 4; ++nt)
#pragma unroll
            for (int q = 0; q < 4; ++q) acc[mt][nt][q] = 0.f;

    const int NCH = D_DIM / 64;   // 6
#pragma unroll
    for (int s = 0; s < NSTAGE - 1; ++s) {
        stage_k64(sb + s * STAGE_BYTES, Abase + s * 64, Bbase + s * 64, D_DIM, tid);
        CP_COMMIT;
    }

#pragma unroll 1
    for (int c = 0; c < NCH; ++c) {
        if (c + NSTAGE - 1 < NCH) {
            stage_k64(sb + ((c + NSTAGE - 1) % NSTAGE) * STAGE_BYTES,
                      Abase + (c + NSTAGE - 1) * 64, Bbase + (c + NSTAGE - 1) * 64,
                      D_DIM, tid);
        }
        CP_COMMIT;
        CP_WAIT2;
        __syncthreads();
        const uint32_t sA = sb + (c % NSTAGE) * STAGE_BYTES;
        compute_chunk(sA, sA + A_BYTES, wm, wn, lane, acc);
        __syncthreads();
    }

    // ---- fused distance epilogue; common (clipped) path has NO MUFU ops ----
    const float CLIPMAX = (1.0f - 1e-5f) * (1.0f - 1e-5f);
    const float sclip = sqrtf(CLIPMAX);
    const float dclip = -__logf(__fdividef(1.0f + sclip, 1.0f - sclip)); // = -2*atanh(sclip)

#pragma unroll
    for (int mt = 0; mt < 4; ++mt) {
        int r0 = rowBase + wm + mt * 16 + (lane >> 2);
        float x2a = g_x2[r0];
        float x2b = g_x2[r0 + 8];
#pragma unroll
        for (int nt = 0; nt < 4; ++nt) {
            int cc = wn + nt * 8 + (lane & 3) * 2;
            float y2a = g_y2[cc], y2b = g_y2[cc + 1];
            float o[4];
#pragma unroll
            for (int q = 0; q < 4; ++q) {
                float xy = acc[mt][nt][q];
                float x2 = (q < 2) ? x2a : x2b;
                float y2 = (q & 1) ? y2b : y2a;
                float sq  = x2 + y2 - 2.0f * xy;
                float den = fmaf(x2, y2, 1.0f - 2.0f * xy);   // > 0 always
                if (sq >= CLIPMAX * den) {
                    o[q] = dclip;                              // ratio clipped high
                } else if (sq <= 0.0f) {
                    o[q] = 0.0f;                               // ratio clipped low
                } else {
                    float s = sqrtf(__fdividef(sq, den));
                    o[q] = -__logf(__fdividef(1.0f + s, 1.0f - s));
                }
            }
            *(float2*)&logits[(size_t)r0 * L_DIM + cc]       = make_float2(o[0], o[1]);
            *(float2*)&logits[(size_t)(r0 + 8) * L_DIM + cc] = make_float2(o[2], o[3]);
        }
    }
}

// ---------------------------------------------------------------------------
extern "C" void kernel_launch(void* const* d_in, const int* in_sizes, int n_in,
                              void* d_out, int out_size)
{
    const float* cls  = (const float*)d_in[0];   // [B, 768]
    const float* Wm   = (const float*)d_in[1];   // [768, 384]
    const float* bias = (const float*)d_in[2];   // [384]
    const float* Y    = (const float*)d_in[3];   // [128, 384]

    const int B = in_sizes[0] / H_DIM;

    float* out = (float*)d_out;
    float* logits = out;                          // [B, 128]
    float* x = out + (size_t)B * L_DIM;           // [B, 384]

    cudaFuncSetAttribute(gemm1_mma, cudaFuncAttributeMaxDynamicSharedMemorySize, SMEM_TOTAL);
    cudaFuncSetAttribute(gemm2_mma, cudaFuncAttributeMaxDynamicSharedMemorySize, SMEM_TOTAL);

    convert_A<<<(int)(((size_t)B * H_DIM / 8) / 256), 256>>>(cls);
    transpose_w_h<<<dim3(H_DIM / 32, D_DIM / 32), dim3(32, 8)>>>(Wm);
    convert_Y<<<L_DIM / 8, 256>>>(Y);
    gemm1_mma<<<dim3(D_DIM / 128, B / 128), 256, SMEM_TOTAL>>>(bias, x);
    expmap_warp<<<B / 8, 256>>>(x);
    gemm2_mma<<<B / 128, 256, SMEM_TOTAL>>>(logits);
}

// round 11
// speedup vs baseline: 2.9600x; 1.0434x over previous
#include <cuda_runtime.h>
#include <cuda_fp16.h>
#include <math.h>
#include <cstdint>

#define H_DIM 768
#define D_DIM 384
#define L_DIM 128
#define B_MAX 32768

// -------- scratch (module globals; no runtime allocation) --------
__device__ float  g_x2[B_MAX];
__device__ float  g_y2[L_DIM];
__device__ __half g_Ah[(size_t)B_MAX * H_DIM];   // cls in fp16
__device__ __half g_Xh[(size_t)B_MAX * D_DIM];   // x in fp16
__device__ __half g_Wth[(size_t)D_DIM * H_DIM];  // W^T in fp16 [D][H]
__device__ __half g_Yh[(size_t)L_DIM * D_DIM];   // Y in fp16 [L][D]

// ---------------- helpers ----------------
__device__ __forceinline__ uint32_t smem_u32(const void* p) {
    uint32_t a;
    asm("{ .reg .u64 t; cvta.to.shared.u64 t, %1; cvt.u32.u64 %0, t; }" : "=r"(a) : "l"(p));
    return a;
}
__device__ __forceinline__ void cp_async16(uint32_t s, const void* g) {
    asm volatile("cp.async.cg.shared.global [%0], [%1], 16;" :: "r"(s), "l"(g));
}
#define CP_COMMIT asm volatile("cp.async.commit_group;" ::: "memory")
#define CP_WAIT1  asm volatile("cp.async.wait_group 1;" ::: "memory")
#define CP_WAIT0  asm volatile("cp.async.wait_group 0;" ::: "memory")
#define CP_WAIT2  asm volatile("cp.async.wait_group 2;" ::: "memory")

__device__ __forceinline__ void mma_fp16(float* d, const uint32_t* a, const uint32_t* b) {
    asm volatile(
        "mma.sync.aligned.m16n8k16.row.col.f32.f16.f16.f32 "
        "{%0,%1,%2,%3}, {%4,%5,%6,%7}, {%8,%9}, {%0,%1,%2,%3};"
        : "+f"(d[0]), "+f"(d[1]), "+f"(d[2]), "+f"(d[3])
        : "r"(a[0]), "r"(a[1]), "r"(a[2]), "r"(a[3]), "r"(b[0]), "r"(b[1]));
}
__device__ __forceinline__ void ldsm_x4(uint32_t addr, uint32_t& r0, uint32_t& r1,
                                        uint32_t& r2, uint32_t& r3) {
    asm volatile("ldmatrix.sync.aligned.m8n8.x4.shared.b16 {%0,%1,%2,%3}, [%4];"
                 : "=r"(r0), "=r"(r1), "=r"(r2), "=r"(r3) : "r"(addr));
}

#define ASTR 72                             // 64 k-halves + 8 pad (144B rows)

// ========== GEMM1: CTA 128x192, warp 64x48, 8 warps, 2-stage k64 ==========
#define G1_A_HALVES (128 * ASTR)
#define G1_A_BYTES  (G1_A_HALVES * 2)       // 18432
#define G1_B_HALVES (192 * ASTR)
#define G1_STAGE_HALVES (G1_A_HALVES + G1_B_HALVES)
#define G1_STAGE_BYTES  (G1_STAGE_HALVES * 2)   // 46080
#define G1_SMEM     (2 * G1_STAGE_BYTES)        // 92160 -> 2 CTAs/SM

__device__ __forceinline__ void g1_stage(uint32_t sstage, const __half* Ag,
                                         const __half* Bg, int tid) {
#pragma unroll
    for (int i = 0; i < 4; ++i) {           // A: 128x64
        int idx = i * 256 + tid;
        int row = idx >> 3, k8 = idx & 7;
        cp_async16(sstage + (uint32_t)((row * ASTR + k8 * 8) * 2),
                   Ag + (size_t)row * H_DIM + k8 * 8);
    }
#pragma unroll
    for (int i = 0; i < 6; ++i) {           // B: 192x64
        int idx = i * 256 + tid;
        int row = idx >> 3, k8 = idx & 7;
        cp_async16(sstage + (uint32_t)(G1_A_BYTES + (row * ASTR + k8 * 8) * 2),
                   Bg + (size_t)row * H_DIM + k8 * 8);
    }
}

// one k64 chunk: 4 k16 steps, warp tile 64x48 (4 A-ldsm + 3 B-ldsm + 24 mma)
__device__ __forceinline__ void g1_compute_chunk(uint32_t sA, uint32_t sB,
                                                 int wm, int wn, int lane,
                                                 float acc[4][6][4]) {
    const int il = lane & 7, g = lane >> 3;
#pragma unroll
    for (int s = 0; s < 4; ++s) {
        const int kb = s * 16;
        uint32_t af[4][4], bf[6][2];
        uint32_t aoff = (uint32_t)(((wm + (g & 1) * 8 + il) * ASTR + kb + (g >> 1) * 8) * 2);
#pragma unroll
        for (int mt = 0; mt < 4; ++mt)
            ldsm_x4(sA + aoff + mt * (16 * ASTR * 2),
                    af[mt][0], af[mt][1], af[mt][2], af[mt][3]);
        uint32_t boff = (uint32_t)(((wn + (g >> 1) * 8 + il) * ASTR + kb + (g & 1) * 8) * 2);
#pragma unroll
        for (int np = 0; np < 3; ++np)
            ldsm_x4(sB + boff + np * (16 * ASTR * 2),
                    bf[np * 2][0], bf[np * 2][1], bf[np * 2 + 1][0], bf[np * 2 + 1][1]);
#pragma unroll
        for (int mt = 0; mt < 4; ++mt)
#pragma unroll
            for (int nt = 0; nt < 6; ++nt)
                mma_fp16(acc[mt][nt], af[mt], bf[nt]);
    }
}

__global__ __launch_bounds__(256, 2)
void gemm1_mma(const float* __restrict__ bias, float* __restrict__ P)
{
    extern __shared__ __half smh[];
    const uint32_t sb = smem_u32(smh);
    const int tid = threadIdx.x, lane = tid & 31, warp = tid >> 5;
    const int wm = (warp >> 2) * 64, wn = (warp & 3) * 48;
    const int rowBase = blockIdx.y * 128, colBase = blockIdx.x * 192;

    const __half* Abase = g_Ah + (size_t)rowBase * H_DIM;
    const __half* Bbase = g_Wth + (size_t)colBase * H_DIM;

    float acc[4][6][4];
#pragma unroll
    for (int mt = 0; mt < 4; ++mt)
#pragma unroll
        for (int nt = 0; nt < 6; ++nt)
#pragma unroll
            for (int q = 0; q < 4; ++q) acc[mt][nt][q] = 0.f;

    const int NCH = H_DIM / 64;   // 12
    g1_stage(sb, Abase, Bbase, tid);
    CP_COMMIT;
    g1_stage(sb + G1_STAGE_BYTES, Abase + 64, Bbase + 64, tid);
    CP_COMMIT;

#pragma unroll 1
    for (int c = 0; c < NCH; ++c) {
        if (c == NCH - 1) { CP_WAIT0; } else { CP_WAIT1; }
        __syncthreads();
        const uint32_t sA = sb + (c & 1) * G1_STAGE_BYTES;
        g1_compute_chunk(sA, sA + G1_A_BYTES, wm, wn, lane, acc);
        if (c + 2 < NCH) {
            __syncthreads();
            g1_stage(sb + (c & 1) * G1_STAGE_BYTES,
                     Abase + (c + 2) * 64, Bbase + (c + 2) * 64, tid);
            CP_COMMIT;
        }
    }

#pragma unroll
    for (int mt = 0; mt < 4; ++mt) {
        int r0 = rowBase + wm + mt * 16 + (lane >> 2);
#pragma unroll
        for (int nt = 0; nt < 6; ++nt) {
            int cc = colBase + wn + nt * 8 + (lane & 3) * 2;
            float b0 = bias[cc], b1 = bias[cc + 1];
            *(float2*)&P[(size_t)r0 * D_DIM + cc] =
                make_float2(acc[mt][nt][0] + b0, acc[mt][nt][1] + b1);
            *(float2*)&P[(size_t)(r0 + 8) * D_DIM + cc] =
                make_float2(acc[mt][nt][2] + b0, acc[mt][nt][3] + b1);
        }
    }
}

// ========== GEMM2 (unchanged structure): 128x128 tile, warp 64x32 ==========
#define A_HALVES (128 * ASTR)
#define A_BYTES  (A_HALVES * 2)
#define STAGE_HALVES (A_HALVES + 128 * ASTR)
#define STAGE_BYTES  (STAGE_HALVES * 2)
#define NSTAGE 3
#define G2_SMEM   (NSTAGE * STAGE_BYTES)

__device__ __forceinline__ void stage_k64(uint32_t sstage, const __half* Ag,
                                          const __half* Bg, int ld, int tid) {
#pragma unroll
    for (int i = 0; i < 4; ++i) {
        int idx = i * 256 + tid;
        int row = idx >> 3, k8 = idx & 7;
        cp_async16(sstage + (uint32_t)((row * ASTR + k8 * 8) * 2),
                   Ag + (size_t)row * ld + k8 * 8);
    }
#pragma unroll
    for (int i = 0; i < 4; ++i) {
        int idx = i * 256 + tid;
        int row = idx >> 3, k8 = idx & 7;
        cp_async16(sstage + (uint32_t)(A_BYTES + (row * ASTR + k8 * 8) * 2),
                   Bg + (size_t)row * ld + k8 * 8);
    }
}

__device__ __forceinline__ void load_frags(uint32_t sA, uint32_t sB, int kb,
                                           int wm, int wn, int lane,
                                           uint32_t af[4][4], uint32_t bf[4][2]) {
    const int il = lane & 7, g = lane >> 3;
    uint32_t aoff = (uint32_t)(((wm + (g & 1) * 8 + il) * ASTR + kb + (g >> 1) * 8) * 2);
#pragma unroll
    for (int mt = 0; mt < 4; ++mt)
        ldsm_x4(sA + aoff + mt * (16 * ASTR * 2),
                af[mt][0], af[mt][1], af[mt][2], af[mt][3]);
    uint32_t boff = (uint32_t)(((wn + (g >> 1) * 8 + il) * ASTR + kb + (g & 1) * 8) * 2);
#pragma unroll
    for (int np = 0; np < 2; ++np)
        ldsm_x4(sB + boff + np * (16 * ASTR * 2),
                bf[np * 2][0], bf[np * 2][1], bf[np * 2 + 1][0], bf[np * 2 + 1][1]);
}
__device__ __forceinline__ void mma_all(uint32_t af[4][4], uint32_t bf[4][2],
                                        float acc[4][4][4]) {
#pragma unroll
    for (int mt = 0; mt < 4; ++mt)
#pragma unroll
        for (int nt = 0; nt < 4; ++nt)
            mma_fp16(acc[mt][nt], af[mt], bf[nt]);
}
__device__ __forceinline__ void compute_chunk(uint32_t sA, uint32_t sB,
                                              int wm, int wn, int lane,
                                              float acc[4][4][4]) {
    uint32_t af[2][4][4], bf[2][4][2];
    load_frags(sA, sB, 0, wm, wn, lane, af[0], bf[0]);
#pragma unroll
    for (int s = 0; s < 4; ++s) {
        if (s < 3)
            load_frags(sA, sB, (s + 1) * 16, wm, wn, lane, af[(s + 1) & 1], bf[(s + 1) & 1]);
        mma_all(af[s & 1], bf[s & 1], acc);
    }
}

// ---------------- conversion kernels ----------------
__global__ void convert_A(const float* __restrict__ A) {
    size_t i = (size_t)blockIdx.x * blockDim.x + threadIdx.x;
    const float4 v0 = ((const float4*)A)[i * 2];
    const float4 v1 = ((const float4*)A)[i * 2 + 1];
    __half2 h0 = __floats2half2_rn(v0.x, v0.y);
    __half2 h1 = __floats2half2_rn(v0.z, v0.w);
    __half2 h2 = __floats2half2_rn(v1.x, v1.y);
    __half2 h3 = __floats2half2_rn(v1.z, v1.w);
    uint4 u;
    u.x = *(uint32_t*)&h0; u.y = *(uint32_t*)&h1;
    u.z = *(uint32_t*)&h2; u.w = *(uint32_t*)&h3;
    ((uint4*)g_Ah)[i] = u;
}

__global__ void transpose_w_h(const float* __restrict__ W) {
    __shared__ float t[32][33];
    int bx = blockIdx.x * 32;
    int by = blockIdx.y * 32;
    int x = threadIdx.x, y = threadIdx.y;
#pragma unroll
    for (int i = 0; i < 32; i += 8)
        t[y + i][x] = W[(size_t)(bx + y + i) * D_DIM + by + x];
    __syncthreads();
#pragma unroll
    for (int i = 0; i < 32; i += 8)
        g_Wth[(size_t)(by + y + i) * H_DIM + bx + x] = __float2half_rn(t[x][y + i]);
}

__global__ __launch_bounds__(256)
void convert_Y(const float* __restrict__ Y) {
    const int warp = threadIdx.x >> 5, lane = threadIdx.x & 31;
    const int row = blockIdx.x * 8 + warp;
    const float* y = Y + (size_t)row * D_DIM;
    __half* yh = g_Yh + (size_t)row * D_DIM;
    float s = 0.f;
#pragma unroll
    for (int j = 0; j < 3; ++j) {
        float4 v = ((const float4*)y)[j * 32 + lane];
        s += v.x * v.x + v.y * v.y + v.z * v.z + v.w * v.w;
        __half2 h0 = __floats2half2_rn(v.x, v.y);
        __half2 h1 = __floats2half2_rn(v.z, v.w);
        uint2 u; u.x = *(uint32_t*)&h0; u.y = *(uint32_t*)&h1;
        ((uint2*)yh)[j * 32 + lane] = u;
    }
#pragma unroll
    for (int o = 16; o > 0; o >>= 1) s += __shfl_xor_sync(0xFFFFFFFFu, s, o);
    if (lane == 0) g_y2[row] = s;
}

// ---------------- expmap0: warp per row ----------------
__global__ __launch_bounds__(256)
void expmap_warp(float* __restrict__ P) {
    const int warp = threadIdx.x >> 5, lane = threadIdx.x & 31;
    const int row = blockIdx.x * 8 + warp;
    float* p = P + (size_t)row * D_DIM;
    __half* xh = g_Xh + (size_t)row * D_DIM;

    float4 v[3];
    float s = 0.f;
#pragma unroll
    for (int j = 0; j < 3; ++j) {
        v[j] = ((const float4*)p)[j * 32 + lane];
        s += v[j].x * v[j].x + v[j].y * v[j].y + v[j].z * v[j].z + v[j].w * v[j].w;
    }
#pragma unroll
    for (int o = 16; o > 0; o >>= 1) s += __shfl_xor_sync(0xFFFFFFFFu, s, o);

    float nsq = s;
    float n = fmaxf(sqrtf(nsq), 1e-15f);
    float scale = tanhf(n) / n;
    if (lane == 0) g_x2[row] = nsq * scale * scale;

#pragma unroll
    for (int j = 0; j < 3; ++j) {
        float4 w = v[j];
        w.x *= scale; w.y *= scale; w.z *= scale; w.w *= scale;
        ((float4*)p)[j * 32 + lane] = w;
        __half2 h0 = __floats2half2_rn(w.x, w.y);
        __half2 h1 = __floats2half2_rn(w.z, w.w);
        uint2 u; u.x = *(uint32_t*)&h0; u.y = *(uint32_t*)&h1;
        ((uint2*)xh)[j * 32 + lane] = u;
    }
}

// ---------------- GEMM2: xy = x @ Y^T, fused Poincare distance -------------
__global__ __launch_bounds__(256, 2)
void gemm2_mma(float* __restrict__ logits)
{
    extern __shared__ __half smh[];
    const uint32_t sb = smem_u32(smh);
    const int tid = threadIdx.x, lane = tid & 31, warp = tid >> 5;
    const int wm = (warp >> 2) * 64, wn = (warp & 3) * 32;
    const int rowBase = blockIdx.x * 128;

    const __half* Abase = g_Xh + (size_t)rowBase * D_DIM;
    const __half* Bbase = g_Yh;

    float acc[4][4][4];
#pragma unroll
    for (int mt = 0; mt < 4; ++mt)
#pragma unroll
        for (int nt = 0; nt < 4; ++nt)
#pragma unroll
            for (int q = 0; q < 4; ++q) acc[mt][nt][q] = 0.f;

    const int NCH = D_DIM / 64;   // 6
#pragma unroll
    for (int s = 0; s < NSTAGE - 1; ++s) {
        stage_k64(sb + s * STAGE_BYTES, Abase + s * 64, Bbase + s * 64, D_DIM, tid);
        CP_COMMIT;
    }

#pragma unroll 1
    for (int c = 0; c < NCH; ++c) {
        if (c + NSTAGE - 1 < NCH) {
            stage_k64(sb + ((c + NSTAGE - 1) % NSTAGE) * STAGE_BYTES,
                      Abase + (c + NSTAGE - 1) * 64, Bbase + (c + NSTAGE - 1) * 64,
                      D_DIM, tid);
        }
        CP_COMMIT;
        CP_WAIT2;
        __syncthreads();
        const uint32_t sA = sb + (c % NSTAGE) * STAGE_BYTES;
        compute_chunk(sA, sA + A_BYTES, wm, wn, lane, acc);
        __syncthreads();
    }

    const float CLIPMAX = (1.0f - 1e-5f) * (1.0f - 1e-5f);
    const float sclip = sqrtf(CLIPMAX);
    const float dclip = -__logf(__fdividef(1.0f + sclip, 1.0f - sclip));

#pragma unroll
    for (int mt = 0; mt < 4; ++mt) {
        int r0 = rowBase + wm + mt * 16 + (lane >> 2);
        float x2a = g_x2[r0];
        float x2b = g_x2[r0 + 8];
#pragma unroll
        for (int nt = 0; nt < 4; ++nt) {
            int cc = wn + nt * 8 + (lane & 3) * 2;
            float y2a = g_y2[cc], y2b = g_y2[cc + 1];
            float o[4];
#pragma unroll
            for (int q = 0; q < 4; ++q) {
                float xy = acc[mt][nt][q];
                float x2 = (q < 2) ? x2a : x2b;
                float y2 = (q & 1) ? y2b : y2a;
                float sq  = x2 + y2 - 2.0f * xy;
                float den = fmaf(x2, y2, 1.0f - 2.0f * xy);
                if (sq >= CLIPMAX * den) {
                    o[q] = dclip;
                } else if (sq <= 0.0f) {
                    o[q] = 0.0f;
                } else {
                    float s = sqrtf(__fdividef(sq, den));
                    o[q] = -__logf(__fdividef(1.0f + s, 1.0f - s));
                }
            }
            *(float2*)&logits[(size_t)r0 * L_DIM + cc]       = make_float2(o[0], o[1]);
            *(float2*)&logits[(size_t)(r0 + 8) * L_DIM + cc] = make_float2(o[2], o[3]);
        }
    }
}

// ---------------------------------------------------------------------------
extern "C" void kernel_launch(void* const* d_in, const int* in_sizes, int n_in,
                              void* d_out, int out_size)
{
    const float* cls  = (const float*)d_in[0];   // [B, 768]
    const float* Wm   = (const float*)d_in[1];   // [768, 384]
    const float* bias = (const float*)d_in[2];   // [384]
    const float* Y    = (const float*)d_in[3];   // [128, 384]

    const int B = in_sizes[0] / H_DIM;

    float* out = (float*)d_out;
    float* logits = out;                          // [B, 128]
    float* x = out + (size_t)B * L_DIM;           // [B, 384]

    cudaFuncSetAttribute(gemm1_mma, cudaFuncAttributeMaxDynamicSharedMemorySize, G1_SMEM);
    cudaFuncSetAttribute(gemm2_mma, cudaFuncAttributeMaxDynamicSharedMemorySize, G2_SMEM);

    convert_A<<<(int)(((size_t)B * H_DIM / 8) / 256), 256>>>(cls);
    transpose_w_h<<<dim3(H_DIM / 32, D_DIM / 32), dim3(32, 8)>>>(Wm);
    convert_Y<<<L_DIM / 8, 256>>>(Y);
    gemm1_mma<<<dim3(D_DIM / 192, B / 128), 256, G1_SMEM>>>(bias, x);
    expmap_warp<<<B / 8, 256>>>(x);
    gemm2_mma<<<B / 128, 256, G2_SMEM>>>(logits);
}